// round 10
// baseline (speedup 1.0000x reference)
#include <cuda_runtime.h>
#include <cstdint>
#include <math.h>

// ---------------- problem constants ----------------
#define NPATCH 500
#define DMODEL 512
#define KDIM   32
#define QKVD   160
#define CATD   1536
#define FFD    2048
#define NLAYER 6
#define NBATCH 32
#define NCLS   256
#define LN_EPS 1e-3f
#define RTOT 875     // rows: scale1 [0,500), scale2 [500,750), scale4 [750,875)

#define GBM 64
#define GBN 64
#define GBK 32
#define NSTG 3
// dynamic smem layout (uint32 words):
//   As(s,m,k) = sm[s*2304 + m*36 + k]          (64 x pad36)
//   Bs(s,k,n) = sm[6912 + s*2304 + k*72 + n]   (32 x pad72)
#define A_STW 2304
#define B_BASE 6912
#define SMEMB 55296

// ---------------- scratch ----------------
__device__ float d_h   [NPATCH * DMODEL];
__device__ float d_pool[375 * DMODEL];
__device__ float d_q   [RTOT * QKVD];
__device__ float d_k   [RTOT * QKVD];
__device__ float d_v   [RTOT * QKVD];
__device__ float d_o   [RTOT * QKVD];
__device__ float d_cat [NPATCH * CATD];
__device__ float d_ff  [NPATCH * FFD];
__device__ float d_part[8 * NPATCH * DMODEL];
__device__ float d_qkvp[6 * RTOT * QKVD];      // [s*3+which][row][c]
__device__ float d_wop [6 * RTOT * DMODEL];    // [s*3+si][row][d]
__device__ float d_cs  [DMODEL];

// ---------------- helpers ----------------
__device__ __forceinline__ uint32_t smem_u32(const void* p) {
    return (uint32_t)__cvta_generic_to_shared(p);
}
__device__ __forceinline__ void cp16(uint32_t dst, const void* src, int sbytes) {
    asm volatile("cp.async.cg.shared.global [%0], [%1], 16, %2;\n"
                 :: "r"(dst), "l"(src), "r"(sbytes));
}
__device__ __forceinline__ void cp_commit() { asm volatile("cp.async.commit_group;\n"); }
__device__ __forceinline__ void mma_tf32(float* c, const uint32_t* a, const uint32_t* b) {
    asm volatile(
        "mma.sync.aligned.m16n8k8.row.col.f32.tf32.tf32.f32 "
        "{%0,%1,%2,%3}, {%4,%5,%6,%7}, {%8,%9}, {%0,%1,%2,%3};"
        : "+f"(c[0]), "+f"(c[1]), "+f"(c[2]), "+f"(c[3])
        : "r"(a[0]), "r"(a[1]), "r"(a[2]), "r"(a[3]), "r"(b[0]), "r"(b[1]));
}
__device__ __forceinline__ void ldsm4(uint32_t& d0, uint32_t& d1, uint32_t& d2, uint32_t& d3,
                                      uint32_t addr) {
    asm volatile("ldmatrix.sync.aligned.m8n8.x4.shared.b16 {%0,%1,%2,%3}, [%4];"
                 : "=r"(d0), "=r"(d1), "=r"(d2), "=r"(d3) : "r"(addr));
}
__device__ __forceinline__ float gelu_f(float x) {
    return 0.5f * x * (1.f + erff(x * 0.70710678118654752f));
}

// ---------------- core GEMM tile (tf32 MMA + ldmatrix A, 3-stage cp.async) ----
// 128 thr, block 64x64xGBK32, 4 warps (2m x 2n), warp tile 32x32.
// A row-major (lda), B row-major (N). kLen % 32 == 0, N % 4 == 0.
__device__ __forceinline__ void gemm_core(
    const float* __restrict__ A, const float* __restrict__ B,
    const float* __restrict__ bias, float* __restrict__ C,
    int M, int N, int lda, int kOff, int kLen,
    int bM, int bN, int act, int addBias)
{
    extern __shared__ uint32_t sm[];

    const int tid  = threadIdx.x;
    const int lane = tid & 31;
    const int warp = tid >> 5;
    const int wm = (warp & 1) << 5;       // 0,32
    const int wn = (warp >> 1) << 5;      // 0,32
    const int g = lane >> 2;              // 0..7
    const int t = lane & 3;               // 0..3

    // ldmatrix per-thread source row/col inside warp's A tile
    const int lrow = lane & 7;
    const int mat  = lane >> 3;           // 0..3
    int aoffw[2];                          // word offsets (without stage/k0)
    #pragma unroll
    for (int i = 0; i < 2; ++i)
        aoffw[i] = (wm + (i << 4) + ((mat & 1) << 3) + lrow) * 36 + ((mat >> 1) << 2);
    const uint32_t smb = smem_u32(sm);

    // A global->smem: row ar = tid>>1 (0..63); k-half (tid&1)*16, 4 cp16 each
    const int ar  = tid >> 1;
    const int akb = (tid & 1) << 4;       // 0 or 16
    const int mrow = min(bM + ar, M - 1);
    const float* aSrc = A + (size_t)mrow * lda + kOff + akb;

    // B global->smem: k-row bk = tid>>2 (0..31); n-quad base (tid&3)*16, 4 cp16 each
    const int bk  = tid >> 2;
    const int bnb = (tid & 3) << 4;       // 0,16,32,48
    const float* bSrc = B + (size_t)(kOff + bk) * N + bN + bnb;
    int bBytes[4];
    #pragma unroll
    for (int q = 0; q < 4; ++q)
        bBytes[q] = ((bN + bnb + q * 4) < N) ? 16 : 0;   // zero-fill OOB columns

    uint32_t aD[NSTG][4], bD[NSTG][4];
    #pragma unroll
    for (int s = 0; s < NSTG; ++s) {
        #pragma unroll
        for (int q = 0; q < 4; ++q) {
            aD[s][q] = smem_u32(&sm[s * A_STW + ar * 36 + akb + q * 4]);
            bD[s][q] = smem_u32(&sm[B_BASE + s * A_STW + bk * 72 + bnb + q * 4]);
        }
    }

    const int T = kLen >> 5;

    // prologue: stages 0,1
    #pragma unroll
    for (int p = 0; p < 2; ++p) {
        const int ko = p << 5;
        #pragma unroll
        for (int q = 0; q < 4; ++q) {
            cp16(aD[p][q], aSrc + ko + q * 4, 16);
            cp16(bD[p][q], bSrc + (size_t)ko * N + q * 4, bBytes[q]);
        }
        cp_commit();
    }

    float acc[2][4][4] = {};

    int stage = 0;
    for (int tt = 0; tt < T; ++tt) {
        if (tt + 1 < T) { asm volatile("cp.async.wait_group 1;\n"); }
        else            { asm volatile("cp.async.wait_group 0;\n"); }
        __syncthreads();

        if (tt + 2 < T) {
            const int ns = (stage + 2 >= NSTG) ? stage + 2 - NSTG : stage + 2;
            const int ko = (tt + 2) << 5;
            #pragma unroll
            for (int q = 0; q < 4; ++q) {
                cp16(aD[ns][q], aSrc + ko + q * 4, 16);
                cp16(bD[ns][q], bSrc + (size_t)ko * N + q * 4, bBytes[q]);
            }
            cp_commit();
        }

        const uint32_t aStage = smb + ((stage * A_STW) << 2);
        const uint32_t* smB = sm + B_BASE + stage * A_STW;
        #pragma unroll
        for (int ks = 0; ks < 4; ++ks) {
            const int k0 = ks << 3;
            uint32_t af[2][4];
            #pragma unroll
            for (int i = 0; i < 2; ++i)
                ldsm4(af[i][0], af[i][1], af[i][2], af[i][3],
                      aStage + ((aoffw[i] + k0) << 2));
            uint32_t bf[4][2];
            #pragma unroll
            for (int j = 0; j < 4; ++j) {
                const int bb = (k0 + t) * 72 + wn + (j << 3) + g;
                bf[j][0] = smB[bb];
                bf[j][1] = smB[bb + 4 * 72];
            }
            #pragma unroll
            for (int i = 0; i < 2; ++i)
                #pragma unroll
                for (int j = 0; j < 4; ++j)
                    mma_tf32(acc[i][j], af[i], bf[j]);
        }
        stage = (stage + 1 >= NSTG) ? 0 : stage + 1;
    }

    // epilogue
    #pragma unroll
    for (int i = 0; i < 2; ++i) {
        const int r0 = bM + wm + (i << 4) + g;
        const int r1 = r0 + 8;
        #pragma unroll
        for (int j = 0; j < 4; ++j) {
            const int col = bN + wn + (j << 3) + (t << 1);
            if (col >= N) continue;
            float b0v = 0.f, b1v = 0.f;
            if (addBias) {
                float2 bb = *(const float2*)(bias + col);
                b0v = bb.x; b1v = bb.y;
            }
            float c0 = acc[i][j][0] + b0v, c1 = acc[i][j][1] + b1v;
            float c2 = acc[i][j][2] + b0v, c3 = acc[i][j][3] + b1v;
            if (act) { c0 = gelu_f(c0); c1 = gelu_f(c1); c2 = gelu_f(c2); c3 = gelu_f(c3); }
            if (r0 < M) *(float2*)(C + (size_t)r0 * N + col) = make_float2(c0, c1);
            if (r1 < M) *(float2*)(C + (size_t)r1 * N + col) = make_float2(c2, c3);
        }
    }
}

// ---------------- GEMM wrappers ----------------
__global__ void __launch_bounds__(128) gemm_std(
    const float* __restrict__ A, const float* __restrict__ B,
    const float* __restrict__ bias, float* __restrict__ C,
    int M, int N, int K, int act)
{
    int bM = blockIdx.y * GBM;
    if (bM >= M) return;
    gemm_core(A, B, bias, C, M, N, K, 0, K, bM, blockIdx.x * GBN, act, 1);
}

__global__ void __launch_bounds__(128) gemm_splitk(
    const float* __restrict__ A, const float* __restrict__ B,
    float* __restrict__ C, int M, int N, int K, int sk)
{
    int bM = blockIdx.y * GBM;
    if (bM >= M) return;
    int z = blockIdx.z;
    gemm_core(A, B, nullptr, C + (size_t)z * M * N, M, N, K, z * sk, sk,
              bM, blockIdx.x * GBN, 0, 0);
}

__constant__ int c_Ms[3]  = {500, 250, 125};
__constant__ int c_ro[3]  = {0, 500, 750};

// qkv split-K: z = s*9 + si*3 + which ; kOff = s*256, kLen = 256
__global__ void __launch_bounds__(128) gemm_qkv(
    const float* __restrict__ h, const float* __restrict__ pool,
    const float* __restrict__ Wq, const float* __restrict__ Wk, const float* __restrict__ Wv,
    float* __restrict__ P)
{
    int z = blockIdx.z;
    int s = z / 9, rem = z - s * 9;
    int si = rem / 3, which = rem - si * 3;
    int M = c_Ms[si];
    int bM = blockIdx.y * GBM;
    if (bM >= M) return;
    const float* A = (si == 0) ? h : (pool + (si == 2 ? 250 * DMODEL : 0));
    const float* W = (which == 0) ? Wq : (which == 1) ? Wk : Wv;
    float* Cb = P + ((size_t)(s * 3 + which) * RTOT + c_ro[si]) * QKVD;
    gemm_core(A, W + (size_t)si * DMODEL * QKVD, nullptr, Cb,
              M, QKVD, DMODEL, s * 256, 256, bM, blockIdx.x * GBN, 0, 0);
}

// wo split-K: z = s*3 + si ; split {0..96, 96..160}
__global__ void __launch_bounds__(128) gemm_wo(
    const float* __restrict__ o, const float* __restrict__ Wo,
    float* __restrict__ P)
{
    int z = blockIdx.z;
    int s = z / 3, si = z - s * 3;
    int M = c_Ms[si];
    int bM = blockIdx.y * GBM;
    if (bM >= M) return;
    int kOff = s ? 96 : 0;
    int kLen = s ? 64 : 96;
    float* Cb = P + ((size_t)(s * 3 + si) * RTOT + c_ro[si]) * DMODEL;
    gemm_core(o + (size_t)c_ro[si] * QKVD, Wo + (size_t)si * QKVD * DMODEL,
              nullptr, Cb, M, DMODEL, QKVD, kOff, kLen, bM, blockIdx.x * GBN, 0, 0);
}

// q/k/v = P[s0]+P[s1]+bias ; grid (875,3) x 160 thr
__global__ void reduce_qkv(const float* __restrict__ P,
                           const float* __restrict__ bq, const float* __restrict__ bk,
                           const float* __restrict__ bv,
                           float* __restrict__ q, float* __restrict__ k,
                           float* __restrict__ v)
{
    int r = blockIdx.x, w = blockIdx.y, c = threadIdx.x;
    int si = (r < 500) ? 0 : (r < 750 ? 1 : 2);
    const float* bias = (w == 0) ? bq : (w == 1) ? bk : bv;
    float val = P[((size_t)(0 + w) * RTOT + r) * QKVD + c]
              + P[((size_t)(3 + w) * RTOT + r) * QKVD + c]
              + bias[si * QKVD + c];
    float* outp = (w == 0) ? q : (w == 1) ? k : v;
    outp[(size_t)r * QKVD + c] = val;
}

// cat[n][si*512+d] = P[s0][si][src]+P[s1][si][src] + bo[si] ; grid 500 x 512
__global__ void reduce_wo_cat(const float* __restrict__ P, const float* __restrict__ bo,
                              float* __restrict__ cat)
{
    int n = blockIdx.x, d = threadIdx.x;
    #pragma unroll
    for (int si = 0; si < 3; ++si) {
        int src = c_ro[si] + (si == 0 ? n : (si == 1 ? (n >> 1) : (n >> 2)));
        float val = P[((size_t)(0 + si) * RTOT + src) * DMODEL + d]
                  + P[((size_t)(3 + si) * RTOT + src) * DMODEL + d]
                  + bo[si * DMODEL + d];
        cat[(size_t)n * CATD + si * DMODEL + d] = val;
    }
}

// ---------------- small kernels ----------------
__global__ void colsum_kernel(const float* __restrict__ W, float* __restrict__ cs) {
    int d = threadIdx.x;
    float s = 0.f;
    #pragma unroll 4
    for (int p = 0; p < 100; p++) s += W[p * DMODEL + d];
    cs[d] = s;
}

__global__ void init_h_kernel(const float* __restrict__ cs, const float* __restrict__ ln_in_b,
                              const float* __restrict__ patch_b, const float* __restrict__ pos,
                              float* __restrict__ h) {
    int n = blockIdx.x, d = threadIdx.x;
    h[n * DMODEL + d] = ln_in_b[0] * cs[d] + patch_b[d] + pos[n * DMODEL + d];
}

__global__ void pool_kernel(const float* __restrict__ h, float* __restrict__ p) {
    int i = blockIdx.x, d = threadIdx.x;
    if (i < 250) {
        p[i * DMODEL + d] = 0.5f * (h[(2 * i) * DMODEL + d] + h[(2 * i + 1) * DMODEL + d]);
    } else {
        int j = i - 250;
        p[i * DMODEL + d] = 0.25f * (h[(4 * j) * DMODEL + d] + h[(4 * j + 1) * DMODEL + d] +
                                     h[(4 * j + 2) * DMODEL + d] + h[(4 * j + 3) * DMODEL + d]);
    }
}

// ---------------- attention: block per (scale, head, 8 queries) ----------------
__global__ void __launch_bounds__(256) attn_kernel(
    const float* __restrict__ q, const float* __restrict__ k,
    const float* __restrict__ v, float* __restrict__ o)
{
    __shared__ float Ks[32][34];
    __shared__ float Vs[32][34];
    __shared__ float OS[8][32][34];

    const int b = blockIdx.x;
    int Ns, ro, h, qg;
    if (b < 315)      { Ns = 500; ro = 0;   h = b / 63;  qg = b % 63; }
    else if (b < 475) { int c = b - 315; Ns = 250; ro = 500; h = c / 32; qg = c % 32; }
    else              { int c = b - 475; Ns = 125; ro = 750; h = c / 16; qg = c % 16; }

    const int wid = threadIdx.x >> 5;
    const int lane = threadIdx.x & 31;
    const int n = qg * 8 + wid;
    const bool valid = n < Ns;
    const int nq = valid ? n : (Ns - 1);
    const float scale = 0.1767766952966369f;  // 1/sqrt(32)

    float2 qr[16];
    {
        const float2* qp = (const float2*)(q + (size_t)(ro + nq) * QKVD + h * KDIM);
        #pragma unroll
        for (int i = 0; i < 16; i++) {
            float2 tq = qp[i];
            qr[i] = make_float2(tq.x * scale, tq.y * scale);
        }
    }

    float mmax = -INFINITY, ssum = 0.f;
    float oa[32];
    #pragma unroll
    for (int d = 0; d < 32; d++) oa[d] = 0.f;

    const int nt = (Ns + 31) >> 5;
    for (int tt = 0; tt < nt; tt++) {
        const int kt = tt << 5;
        {
            const int m = threadIdx.x >> 3;
            const int dq = (threadIdx.x & 7) << 2;
            const int row = min(kt + m, Ns - 1);
            const float4 kk = *(const float4*)(k + (size_t)(ro + row) * QKVD + h * KDIM + dq);
            const float4 vv = *(const float4*)(v + (size_t)(ro + row) * QKVD + h * KDIM + dq);
            *(float2*)&Ks[m][dq]     = make_float2(kk.x, kk.y);
            *(float2*)&Ks[m][dq + 2] = make_float2(kk.z, kk.w);
            *(float2*)&Vs[m][dq]     = make_float2(vv.x, vv.y);
            *(float2*)&Vs[m][dq + 2] = make_float2(vv.z, vv.w);
        }
        __syncthreads();

        float s0 = 0.f, s1 = 0.f;
        #pragma unroll
        for (int i = 0; i < 16; i++) {
            float2 kk = *(const float2*)&Ks[lane][2 * i];
            s0 = fmaf(qr[i].x, kk.x, s0);
            s1 = fmaf(qr[i].y, kk.y, s1);
        }
        float s = s0 + s1;
        if (kt + lane >= Ns) s = -INFINITY;

        float nm = fmaxf(mmax, s);
        float corr = __expf(mmax - nm);
        float p = __expf(s - nm);
        ssum = ssum * corr + p;
        #pragma unroll
        for (int i = 0; i < 16; i++) {
            float2 vv = *(const float2*)&Vs[lane][2 * i];
            oa[2 * i]     = oa[2 * i]     * corr + p * vv.x;
            oa[2 * i + 1] = oa[2 * i + 1] * corr + p * vv.y;
        }
        mmax = nm;
        __syncthreads();
    }

    float gm = mmax;
    #pragma unroll
    for (int off = 16; off; off >>= 1) gm = fmaxf(gm, __shfl_xor_sync(0xffffffffu, gm, off));
    float c = __expf(mmax - gm);
    float ss = ssum * c;
    #pragma unroll
    for (int off = 16; off; off >>= 1) ss += __shfl_xor_sync(0xffffffffu, ss, off);

    #pragma unroll
    for (int i = 0; i < 16; i++)
        *(float2*)&OS[wid][lane][2 * i] = make_float2(oa[2 * i] * c, oa[2 * i + 1] * c);
    __syncwarp();

    float accd = 0.f;
    #pragma unroll
    for (int m = 0; m < 32; m++) accd += OS[wid][m][lane];
    if (valid)
        o[(size_t)(ro + n) * QKVD + h * KDIM + lane] = accd / ss;
}

// h[n,:] = LayerNorm(h[n,:] + bias + sum_{s<S} part[s][n,:]) * g + b
__global__ void reduce_add_ln_kernel(const float* __restrict__ part, int S,
                                     const float* __restrict__ bias,
                                     float* __restrict__ h,
                                     const float* __restrict__ g,
                                     const float* __restrict__ b) {
    int n = blockIdx.x, t = threadIdx.x;
    __shared__ float red[8];
    __shared__ float stat;
    float v0 = h[n * DMODEL + t]       + bias[t];
    float v1 = h[n * DMODEL + t + 256] + bias[t + 256];
    for (int s = 0; s < S; s++) {
        v0 += part[(size_t)s * NPATCH * DMODEL + n * DMODEL + t];
        v1 += part[(size_t)s * NPATCH * DMODEL + n * DMODEL + t + 256];
    }

    float s = v0 + v1;
    #pragma unroll
    for (int o = 16; o; o >>= 1) s += __shfl_xor_sync(0xffffffffu, s, o);
    if ((t & 31) == 0) red[t >> 5] = s;
    __syncthreads();
    if (t < 32) {
        float x = (t < 8) ? red[t] : 0.f;
        #pragma unroll
        for (int o = 4; o; o >>= 1) x += __shfl_xor_sync(0xffffffffu, x, o);
        if (t == 0) stat = x / (float)DMODEL;
    }
    __syncthreads();
    float mean = stat;
    float dd0 = v0 - mean, dd1 = v1 - mean;

    __syncthreads();
    float vs = dd0 * dd0 + dd1 * dd1;
    #pragma unroll
    for (int o = 16; o; o >>= 1) vs += __shfl_xor_sync(0xffffffffu, vs, o);
    if ((t & 31) == 0) red[t >> 5] = vs;
    __syncthreads();
    if (t < 32) {
        float x = (t < 8) ? red[t] : 0.f;
        #pragma unroll
        for (int o = 4; o; o >>= 1) x += __shfl_xor_sync(0xffffffffu, x, o);
        if (t == 0) stat = rsqrtf(x / (float)DMODEL + LN_EPS);
    }
    __syncthreads();
    float rstd = stat;
    h[n * DMODEL + t]       = dd0 * rstd * g[t]       + b[t];
    h[n * DMODEL + t + 256] = dd1 * rstd * g[t + 256] + b[t + 256];
}

// fused global-mean-pool + head + softmax + broadcast
__global__ void head_kernel(const float* __restrict__ h, const float* __restrict__ W,
                            const float* __restrict__ b, float* __restrict__ out) {
    __shared__ float gs[DMODEL];
    __shared__ float red[8];
    __shared__ float stat;
    int t = threadIdx.x;  // 256
    {
        float s0 = 0.f, s1 = 0.f;
        for (int n = 0; n < NPATCH; n++) {
            s0 += h[n * DMODEL + t];
            s1 += h[n * DMODEL + t + 256];
        }
        gs[t] = s0 / (float)NPATCH;
        gs[t + 256] = s1 / (float)NPATCH;
    }
    __syncthreads();
    float acc = b[t];
    #pragma unroll 4
    for (int d = 0; d < DMODEL; d++) acc += gs[d] * W[d * NCLS + t];

    float m = acc;
    #pragma unroll
    for (int o = 16; o; o >>= 1) m = fmaxf(m, __shfl_xor_sync(0xffffffffu, m, o));
    if ((t & 31) == 0) red[t >> 5] = m;
    __syncthreads();
    if (t < 32) {
        float x = (t < 8) ? red[t] : -INFINITY;
        #pragma unroll
        for (int o = 4; o; o >>= 1) x = fmaxf(x, __shfl_xor_sync(0xffffffffu, x, o));
        if (t == 0) stat = x;
    }
    __syncthreads();
    float e = expf(acc - stat);
    __syncthreads();
    float s = e;
    #pragma unroll
    for (int o = 16; o; o >>= 1) s += __shfl_xor_sync(0xffffffffu, s, o);
    if ((t & 31) == 0) red[t >> 5] = s;
    __syncthreads();
    if (t < 32) {
        float x = (t < 8) ? red[t] : 0.f;
        #pragma unroll
        for (int o = 4; o; o >>= 1) x += __shfl_xor_sync(0xffffffffu, x, o);
        if (t == 0) stat = x;
    }
    __syncthreads();
    float p = e / stat;
    for (int bb = 0; bb < NBATCH; bb++) out[bb * NCLS + t] = p;
}

// ---------------- host launcher ----------------
extern "C" void kernel_launch(void* const* d_in, const int* in_sizes, int n_in,
                              void* d_out, int out_size) {
    const float* ln_in_b = (const float*)d_in[2];
    const float* patch_W = (const float*)d_in[3];
    const float* patch_b = (const float*)d_in[4];
    const float* pos_emb = (const float*)d_in[5];
    const float* Wq = (const float*)d_in[6];
    const float* bq = (const float*)d_in[7];
    const float* Wk = (const float*)d_in[8];
    const float* bk = (const float*)d_in[9];
    const float* Wv = (const float*)d_in[10];
    const float* bv = (const float*)d_in[11];
    const float* Wo = (const float*)d_in[12];
    const float* bo = (const float*)d_in[13];
    const float* Wc = (const float*)d_in[14];
    const float* bc = (const float*)d_in[15];
    const float* ln1_g = (const float*)d_in[16];
    const float* ln1_b = (const float*)d_in[17];
    const float* W1 = (const float*)d_in[18];
    const float* b1 = (const float*)d_in[19];
    const float* W2 = (const float*)d_in[20];
    const float* b2 = (const float*)d_in[21];
    const float* ln2_g = (const float*)d_in[22];
    const float* ln2_b = (const float*)d_in[23];
    const float* head_W = (const float*)d_in[24];
    const float* head_b = (const float*)d_in[25];
    float* out = (float*)d_out;

    static bool attrDone = false;
    if (!attrDone) {
        cudaFuncSetAttribute(gemm_std, cudaFuncAttributeMaxDynamicSharedMemorySize, SMEMB);
        cudaFuncSetAttribute(gemm_splitk, cudaFuncAttributeMaxDynamicSharedMemorySize, SMEMB);
        cudaFuncSetAttribute(gemm_qkv, cudaFuncAttributeMaxDynamicSharedMemorySize, SMEMB);
        cudaFuncSetAttribute(gemm_wo, cudaFuncAttributeMaxDynamicSharedMemorySize, SMEMB);
        attrDone = true;
    }

    float *hp, *pp, *qp, *kp, *vp, *op, *catp, *ffp, *partp, *csp, *qkvpp, *wopp;
    cudaGetSymbolAddress((void**)&hp,  d_h);
    cudaGetSymbolAddress((void**)&pp,  d_pool);
    cudaGetSymbolAddress((void**)&qp,  d_q);
    cudaGetSymbolAddress((void**)&kp,  d_k);
    cudaGetSymbolAddress((void**)&vp,  d_v);
    cudaGetSymbolAddress((void**)&op,  d_o);
    cudaGetSymbolAddress((void**)&catp, d_cat);
    cudaGetSymbolAddress((void**)&ffp, d_ff);
    cudaGetSymbolAddress((void**)&partp, d_part);
    cudaGetSymbolAddress((void**)&csp, d_cs);
    cudaGetSymbolAddress((void**)&qkvpp, d_qkvp);
    cudaGetSymbolAddress((void**)&wopp, d_wop);

    colsum_kernel<<<1, DMODEL>>>(patch_W, csp);
    init_h_kernel<<<NPATCH, DMODEL>>>(csp, ln_in_b, patch_b, pos_emb, hp);

    for (int l = 0; l < NLAYER; l++) {
        size_t wqkv = (size_t)l * 3 * DMODEL * QKVD;
        size_t bqkv = (size_t)l * 3 * QKVD;
        size_t wwo  = (size_t)l * 3 * QKVD * DMODEL;
        size_t bwo  = (size_t)l * 3 * DMODEL;

        pool_kernel<<<375, DMODEL>>>(hp, pp);
        gemm_qkv<<<dim3(3, 8, 18), 128, SMEMB>>>(hp, pp,
            Wq + wqkv, Wk + wqkv, Wv + wqkv, qkvpp);
        reduce_qkv<<<dim3(RTOT, 3), QKVD>>>(qkvpp, bq + bqkv, bk + bqkv, bv + bqkv,
                                            qp, kp, vp);
        attn_kernel<<<555, 256>>>(qp, kp, vp, op);
        gemm_wo<<<dim3(8, 8, 6), 128, SMEMB>>>(op, Wo + wwo, wopp);
        reduce_wo_cat<<<NPATCH, DMODEL>>>(wopp, bo + bwo, catp);

        // combine: split-K 6x256 -> partials -> fused reduce+bias+residual+LN
        gemm_splitk<<<dim3(8, 8, 6), 128, SMEMB>>>(catp, Wc + (size_t)l * CATD * DMODEL,
                                                   partp, NPATCH, DMODEL, CATD, 256);
        reduce_add_ln_kernel<<<NPATCH, 256>>>(partp, 6, bc + (size_t)l * DMODEL, hp,
                                              ln1_g + l * DMODEL, ln1_b + l * DMODEL);

        // FFN
        gemm_std<<<dim3(32, 8), 128, SMEMB>>>(hp, W1 + (size_t)l * DMODEL * FFD,
                                              b1 + (size_t)l * FFD, ffp,
                                              NPATCH, FFD, DMODEL, 1);
        gemm_splitk<<<dim3(8, 8, 8), 128, SMEMB>>>(ffp, W2 + (size_t)l * FFD * DMODEL,
                                                   partp, NPATCH, DMODEL, FFD, 256);
        reduce_add_ln_kernel<<<NPATCH, 256>>>(partp, 8, b2 + (size_t)l * DMODEL, hp,
                                              ln2_g + l * DMODEL, ln2_b + l * DMODEL);
    }

    head_kernel<<<1, NCLS>>>(hp, head_W, head_b, out);
}

// round 11
// speedup vs baseline: 1.2092x; 1.2092x over previous
#include <cuda_runtime.h>
#include <cstdint>
#include <math.h>

// ---------------- problem constants ----------------
#define NPATCH 500
#define DMODEL 512
#define KDIM   32
#define QKVD   160
#define CATD   1536
#define FFD    2048
#define NLAYER 6
#define NBATCH 32
#define NCLS   256
#define LN_EPS 1e-3f
#define RTOT 875     // rows: scale1 [0,500), scale2 [500,750), scale4 [750,875)

#define GBM 64
#define GBN 64
#define GBK 32
#define NSTG 3
// dynamic smem layout (uint32 words):
//   As(s,m,k) = sm[s*2304 + m*36 + k]          (64 x pad36)
//   Bs(s,k,n) = sm[6912 + s*2304 + k*72 + n]   (32 x pad72)
#define A_STW 2304
#define B_BASE 6912
#define SMEMB 55296

// ---------------- scratch ----------------
__device__ float d_h   [NPATCH * DMODEL];
__device__ float d_pool[375 * DMODEL];
__device__ float d_q   [RTOT * QKVD];
__device__ float d_k   [RTOT * QKVD];
__device__ float d_v   [RTOT * QKVD];
__device__ float d_o   [RTOT * QKVD];
__device__ float d_ao  [RTOT * DMODEL];
__device__ float d_ff  [NPATCH * FFD];
__device__ float d_part[8 * NPATCH * DMODEL];
__device__ float d_qkvp[6 * RTOT * QKVD];      // [s*3+which][row][c]
__device__ float d_wop [6 * RTOT * DMODEL];    // [s*3+si][row][d]
__device__ float d_cs  [DMODEL];

// ---------------- helpers ----------------
__device__ __forceinline__ uint32_t smem_u32(const void* p) {
    return (uint32_t)__cvta_generic_to_shared(p);
}
__device__ __forceinline__ void cp16(uint32_t dst, const void* src, int sbytes) {
    asm volatile("cp.async.cg.shared.global [%0], [%1], 16, %2;\n"
                 :: "r"(dst), "l"(src), "r"(sbytes));
}
__device__ __forceinline__ void cp_commit() { asm volatile("cp.async.commit_group;\n"); }
__device__ __forceinline__ void mma_tf32(float* c, const uint32_t* a, const uint32_t* b) {
    asm volatile(
        "mma.sync.aligned.m16n8k8.row.col.f32.tf32.tf32.f32 "
        "{%0,%1,%2,%3}, {%4,%5,%6,%7}, {%8,%9}, {%0,%1,%2,%3};"
        : "+f"(c[0]), "+f"(c[1]), "+f"(c[2]), "+f"(c[3])
        : "r"(a[0]), "r"(a[1]), "r"(a[2]), "r"(a[3]), "r"(b[0]), "r"(b[1]));
}
__device__ __forceinline__ void ldsm4(uint32_t& d0, uint32_t& d1, uint32_t& d2, uint32_t& d3,
                                      uint32_t addr) {
    asm volatile("ldmatrix.sync.aligned.m8n8.x4.shared.b16 {%0,%1,%2,%3}, [%4];"
                 : "=r"(d0), "=r"(d1), "=r"(d2), "=r"(d3) : "r"(addr));
}
__device__ __forceinline__ float gelu_f(float x) {
    return 0.5f * x * (1.f + erff(x * 0.70710678118654752f));
}

// ---------------- core GEMM tile (tf32 MMA + ldmatrix A, 3-stage cp.async) ----
// 256 thr, block 64x64xGBK32, 8 warps (2m x 4n), warp tile 32x16.
// A row-major (lda), B row-major (N). kLen % 32 == 0, N % 4 == 0.
__device__ __forceinline__ void gemm_core(
    const float* __restrict__ A, const float* __restrict__ B,
    const float* __restrict__ bias, float* __restrict__ C,
    int M, int N, int lda, int kOff, int kLen,
    int bM, int bN, int act, int addBias)
{
    extern __shared__ uint32_t sm[];

    const int tid  = threadIdx.x;
    const int lane = tid & 31;
    const int warp = tid >> 5;
    const int wm = (warp & 1) << 5;       // 0,32
    const int wn = (warp >> 1) << 4;      // 0,16,32,48
    const int g = lane >> 2;              // 0..7
    const int t = lane & 3;               // 0..3

    // ldmatrix per-thread source row/col inside warp's A tile
    const int lrow = lane & 7;
    const int mat  = lane >> 3;           // 0..3
    int aoffw[2];                          // word offsets (without stage/k0)
    #pragma unroll
    for (int i = 0; i < 2; ++i)
        aoffw[i] = (wm + (i << 4) + ((mat & 1) << 3) + lrow) * 36 + ((mat >> 1) << 2);
    const uint32_t smb = smem_u32(sm);

    // A global->smem: row ar (0..63), k quads akq, akq+16
    const int ar  = tid >> 2;             // 0..63
    const int akq = (tid & 3) << 2;       // 0,4,8,12
    const int mrow = min(bM + ar, M - 1);
    const float* aSrc = A + (size_t)mrow * lda + kOff + akq;

    // B global->smem: k rows bk, bk+16 ; n-quad bnq
    const int bk  = tid >> 4;             // 0..15
    const int bnq = (tid & 15) << 2;      // 0..60
    const int bBytes = ((bN + bnq) < N) ? 16 : 0;   // zero-fill OOB columns
    const float* bSrc = B + (size_t)(kOff + bk) * N + bN + bnq;

    uint32_t aD0[NSTG], aD1[NSTG], bD0[NSTG], bD1[NSTG];
    #pragma unroll
    for (int s = 0; s < NSTG; ++s) {
        aD0[s] = smem_u32(&sm[s * A_STW + ar * 36 + akq]);
        aD1[s] = smem_u32(&sm[s * A_STW + ar * 36 + akq + 16]);
        bD0[s] = smem_u32(&sm[B_BASE + s * A_STW + bk * 72 + bnq]);
        bD1[s] = smem_u32(&sm[B_BASE + s * A_STW + (bk + 16) * 72 + bnq]);
    }

    const int T = kLen >> 5;

    // prologue: stages 0,1
    #pragma unroll
    for (int p = 0; p < 2; ++p) {
        const int ko = p << 5;
        cp16(aD0[p], aSrc + ko, 16);
        cp16(aD1[p], aSrc + ko + 16, 16);
        cp16(bD0[p], bSrc + (size_t)ko * N, bBytes);
        cp16(bD1[p], bSrc + (size_t)(ko + 16) * N, bBytes);
        cp_commit();
    }

    float acc[2][2][4] = {};

    int stage = 0;
    for (int tt = 0; tt < T; ++tt) {
        if (tt + 1 < T) { asm volatile("cp.async.wait_group 1;\n"); }
        else            { asm volatile("cp.async.wait_group 0;\n"); }
        __syncthreads();

        if (tt + 2 < T) {
            const int ns = (stage + 2 >= NSTG) ? stage + 2 - NSTG : stage + 2;
            const int ko = (tt + 2) << 5;
            cp16(aD0[ns], aSrc + ko, 16);
            cp16(aD1[ns], aSrc + ko + 16, 16);
            cp16(bD0[ns], bSrc + (size_t)ko * N, bBytes);
            cp16(bD1[ns], bSrc + (size_t)(ko + 16) * N, bBytes);
            cp_commit();
        }

        const uint32_t aStage = smb + ((stage * A_STW) << 2);
        const uint32_t* smB = sm + B_BASE + stage * A_STW;
        #pragma unroll
        for (int ks = 0; ks < 4; ++ks) {
            const int k0 = ks << 3;
            uint32_t af[2][4];
            #pragma unroll
            for (int i = 0; i < 2; ++i)
                ldsm4(af[i][0], af[i][1], af[i][2], af[i][3],
                      aStage + ((aoffw[i] + k0) << 2));
            uint32_t bf[2][2];
            #pragma unroll
            for (int j = 0; j < 2; ++j) {
                const int bb = (k0 + t) * 72 + wn + (j << 3) + g;
                bf[j][0] = smB[bb];
                bf[j][1] = smB[bb + 4 * 72];
            }
            #pragma unroll
            for (int i = 0; i < 2; ++i)
                #pragma unroll
                for (int j = 0; j < 2; ++j)
                    mma_tf32(acc[i][j], af[i], bf[j]);
        }
        stage = (stage + 1 >= NSTG) ? 0 : stage + 1;
    }

    // epilogue
    #pragma unroll
    for (int i = 0; i < 2; ++i) {
        const int r0 = bM + wm + (i << 4) + g;
        const int r1 = r0 + 8;
        #pragma unroll
        for (int j = 0; j < 2; ++j) {
            const int col = bN + wn + (j << 3) + (t << 1);
            if (col >= N) continue;
            float b0v = 0.f, b1v = 0.f;
            if (addBias) {
                float2 bb = *(const float2*)(bias + col);
                b0v = bb.x; b1v = bb.y;
            }
            float c0 = acc[i][j][0] + b0v, c1 = acc[i][j][1] + b1v;
            float c2 = acc[i][j][2] + b0v, c3 = acc[i][j][3] + b1v;
            if (act) { c0 = gelu_f(c0); c1 = gelu_f(c1); c2 = gelu_f(c2); c3 = gelu_f(c3); }
            if (r0 < M) *(float2*)(C + (size_t)r0 * N + col) = make_float2(c0, c1);
            if (r1 < M) *(float2*)(C + (size_t)r1 * N + col) = make_float2(c2, c3);
        }
    }
}

// ---------------- GEMM wrappers ----------------
__global__ void __launch_bounds__(256) gemm_std(
    const float* __restrict__ A, const float* __restrict__ B,
    const float* __restrict__ bias, float* __restrict__ C,
    int M, int N, int K, int act)
{
    int bM = blockIdx.y * GBM;
    if (bM >= M) return;
    gemm_core(A, B, bias, C, M, N, K, 0, K, bM, blockIdx.x * GBN, act, 1);
}

__global__ void __launch_bounds__(256) gemm_splitk(
    const float* __restrict__ A, const float* __restrict__ B,
    float* __restrict__ C, int M, int N, int K, int sk)
{
    int bM = blockIdx.y * GBM;
    if (bM >= M) return;
    int z = blockIdx.z;
    gemm_core(A, B, nullptr, C + (size_t)z * M * N, M, N, K, z * sk, sk,
              bM, blockIdx.x * GBN, 0, 0);
}

__constant__ int c_Ms[3]  = {500, 250, 125};
__constant__ int c_ro[3]  = {0, 500, 750};

// qkv split-K: z = s*9 + si*3 + which ; kOff = s*256, kLen = 256
__global__ void __launch_bounds__(256) gemm_qkv(
    const float* __restrict__ h, const float* __restrict__ pool,
    const float* __restrict__ Wq, const float* __restrict__ Wk, const float* __restrict__ Wv,
    float* __restrict__ P)
{
    int z = blockIdx.z;
    int s = z / 9, rem = z - s * 9;
    int si = rem / 3, which = rem - si * 3;
    int M = c_Ms[si];
    int bM = blockIdx.y * GBM;
    if (bM >= M) return;
    const float* A = (si == 0) ? h : (pool + (si == 2 ? 250 * DMODEL : 0));
    const float* W = (which == 0) ? Wq : (which == 1) ? Wk : Wv;
    float* Cb = P + ((size_t)(s * 3 + which) * RTOT + c_ro[si]) * QKVD;
    gemm_core(A, W + (size_t)si * DMODEL * QKVD, nullptr, Cb,
              M, QKVD, DMODEL, s * 256, 256, bM, blockIdx.x * GBN, 0, 0);
}

// wo split-K: z = s*3 + si ; split {0..96, 96..160}
__global__ void __launch_bounds__(256) gemm_wo(
    const float* __restrict__ o, const float* __restrict__ Wo,
    float* __restrict__ P)
{
    int z = blockIdx.z;
    int s = z / 3, si = z - s * 3;
    int M = c_Ms[si];
    int bM = blockIdx.y * GBM;
    if (bM >= M) return;
    int kOff = s ? 96 : 0;
    int kLen = s ? 64 : 96;
    float* Cb = P + ((size_t)(s * 3 + si) * RTOT + c_ro[si]) * DMODEL;
    gemm_core(o + (size_t)c_ro[si] * QKVD, Wo + (size_t)si * QKVD * DMODEL,
              nullptr, Cb, M, DMODEL, QKVD, kOff, kLen, bM, blockIdx.x * GBN, 0, 0);
}

// combine per-scale on POOLED rows: z = si*2 + s ; A = ao rows of scale si
// partial -> part[z][0:M_si][512]
__global__ void __launch_bounds__(256) gemm_comb(
    const float* __restrict__ ao, const float* __restrict__ Wc,
    float* __restrict__ P)
{
    int z = blockIdx.z;
    int si = z >> 1, s = z & 1;
    int M = c_Ms[si];
    int bM = blockIdx.y * GBM;
    if (bM >= M) return;
    gemm_core(ao + (size_t)c_ro[si] * DMODEL,
              Wc + (size_t)si * DMODEL * DMODEL,   // rows si*512..si*512+511 of Wc
              nullptr, P + (size_t)z * NPATCH * DMODEL,
              M, DMODEL, DMODEL, s * 256, 256, bM, blockIdx.x * GBN, 0, 0);
}

// q/k/v = P[s0]+P[s1]+bias ; grid (875,3) x 160 thr
__global__ void reduce_qkv(const float* __restrict__ P,
                           const float* __restrict__ bq, const float* __restrict__ bk,
                           const float* __restrict__ bv,
                           float* __restrict__ q, float* __restrict__ k,
                           float* __restrict__ v)
{
    int r = blockIdx.x, w = blockIdx.y, c = threadIdx.x;
    int si = (r < 500) ? 0 : (r < 750 ? 1 : 2);
    const float* bias = (w == 0) ? bq : (w == 1) ? bk : bv;
    float val = P[((size_t)(0 + w) * RTOT + r) * QKVD + c]
              + P[((size_t)(3 + w) * RTOT + r) * QKVD + c]
              + bias[si * QKVD + c];
    float* outp = (w == 0) ? q : (w == 1) ? k : v;
    outp[(size_t)r * QKVD + c] = val;
}

// ao[r][d] = P[s0][r][d] + P[s1][r][d] + bo[si][d] ; grid 875 x 512
__global__ void reduce_wo(const float* __restrict__ P, const float* __restrict__ bo,
                          float* __restrict__ ao)
{
    int r = blockIdx.x, d = threadIdx.x;
    int si = (r < 500) ? 0 : (r < 750 ? 1 : 2);
    ao[(size_t)r * DMODEL + d] = P[((size_t)(0 + si) * RTOT + r) * DMODEL + d]
                               + P[((size_t)(3 + si) * RTOT + r) * DMODEL + d]
                               + bo[si * DMODEL + d];
}

// ---------------- small kernels ----------------
__global__ void colsum_kernel(const float* __restrict__ W, float* __restrict__ cs) {
    int d = threadIdx.x;
    float s = 0.f;
    #pragma unroll 4
    for (int p = 0; p < 100; p++) s += W[p * DMODEL + d];
    cs[d] = s;
}

__global__ void init_h_kernel(const float* __restrict__ cs, const float* __restrict__ ln_in_b,
                              const float* __restrict__ patch_b, const float* __restrict__ pos,
                              float* __restrict__ h) {
    int n = blockIdx.x, d = threadIdx.x;
    h[n * DMODEL + d] = ln_in_b[0] * cs[d] + patch_b[d] + pos[n * DMODEL + d];
}

__global__ void pool_kernel(const float* __restrict__ h, float* __restrict__ p) {
    int i = blockIdx.x, d = threadIdx.x;
    if (i < 250) {
        p[i * DMODEL + d] = 0.5f * (h[(2 * i) * DMODEL + d] + h[(2 * i + 1) * DMODEL + d]);
    } else {
        int j = i - 250;
        p[i * DMODEL + d] = 0.25f * (h[(4 * j) * DMODEL + d] + h[(4 * j + 1) * DMODEL + d] +
                                     h[(4 * j + 2) * DMODEL + d] + h[(4 * j + 3) * DMODEL + d]);
    }
}

// ---------------- attention: block per (scale, head, 8 queries) ----------------
__global__ void __launch_bounds__(256) attn_kernel(
    const float* __restrict__ q, const float* __restrict__ k,
    const float* __restrict__ v, float* __restrict__ o)
{
    __shared__ float Ks[32][34];
    __shared__ float Vs[32][34];
    __shared__ float OS[8][32][34];

    const int b = blockIdx.x;
    int Ns, ro, h, qg;
    if (b < 315)      { Ns = 500; ro = 0;   h = b / 63;  qg = b % 63; }
    else if (b < 475) { int c = b - 315; Ns = 250; ro = 500; h = c / 32; qg = c % 32; }
    else              { int c = b - 475; Ns = 125; ro = 750; h = c / 16; qg = c % 16; }

    const int wid = threadIdx.x >> 5;
    const int lane = threadIdx.x & 31;
    const int n = qg * 8 + wid;
    const bool valid = n < Ns;
    const int nq = valid ? n : (Ns - 1);
    const float scale = 0.1767766952966369f;  // 1/sqrt(32)

    float2 qr[16];
    {
        const float2* qp = (const float2*)(q + (size_t)(ro + nq) * QKVD + h * KDIM);
        #pragma unroll
        for (int i = 0; i < 16; i++) {
            float2 tq = qp[i];
            qr[i] = make_float2(tq.x * scale, tq.y * scale);
        }
    }

    float mmax = -INFINITY, ssum = 0.f;
    float oa[32];
    #pragma unroll
    for (int d = 0; d < 32; d++) oa[d] = 0.f;

    const int nt = (Ns + 31) >> 5;
    for (int tt = 0; tt < nt; tt++) {
        const int kt = tt << 5;
        {
            const int m = threadIdx.x >> 3;
            const int dq = (threadIdx.x & 7) << 2;
            const int row = min(kt + m, Ns - 1);
            const float4 kk = *(const float4*)(k + (size_t)(ro + row) * QKVD + h * KDIM + dq);
            const float4 vv = *(const float4*)(v + (size_t)(ro + row) * QKVD + h * KDIM + dq);
            *(float2*)&Ks[m][dq]     = make_float2(kk.x, kk.y);
            *(float2*)&Ks[m][dq + 2] = make_float2(kk.z, kk.w);
            *(float2*)&Vs[m][dq]     = make_float2(vv.x, vv.y);
            *(float2*)&Vs[m][dq + 2] = make_float2(vv.z, vv.w);
        }
        __syncthreads();

        float s0 = 0.f, s1 = 0.f;
        #pragma unroll
        for (int i = 0; i < 16; i++) {
            float2 kk = *(const float2*)&Ks[lane][2 * i];
            s0 = fmaf(qr[i].x, kk.x, s0);
            s1 = fmaf(qr[i].y, kk.y, s1);
        }
        float s = s0 + s1;
        if (kt + lane >= Ns) s = -INFINITY;

        float nm = fmaxf(mmax, s);
        float corr = __expf(mmax - nm);
        float p = __expf(s - nm);
        ssum = ssum * corr + p;
        #pragma unroll
        for (int i = 0; i < 16; i++) {
            float2 vv = *(const float2*)&Vs[lane][2 * i];
            oa[2 * i]     = oa[2 * i]     * corr + p * vv.x;
            oa[2 * i + 1] = oa[2 * i + 1] * corr + p * vv.y;
        }
        mmax = nm;
        __syncthreads();
    }

    float gm = mmax;
    #pragma unroll
    for (int off = 16; off; off >>= 1) gm = fmaxf(gm, __shfl_xor_sync(0xffffffffu, gm, off));
    float c = __expf(mmax - gm);
    float ss = ssum * c;
    #pragma unroll
    for (int off = 16; off; off >>= 1) ss += __shfl_xor_sync(0xffffffffu, ss, off);

    #pragma unroll
    for (int i = 0; i < 16; i++)
        *(float2*)&OS[wid][lane][2 * i] = make_float2(oa[2 * i] * c, oa[2 * i + 1] * c);
    __syncwarp();

    float accd = 0.f;
    #pragma unroll
    for (int m = 0; m < 32; m++) accd += OS[wid][m][lane];
    if (valid)
        o[(size_t)(ro + n) * QKVD + h * KDIM + lane] = accd / ss;
}

// h[n,:] = LayerNorm(h[n,:] + bias + comb partials with upsample) * g + b
// P layout: [si*2+s][M_si rows][512]; rows indexed n, n>>1, n>>2 per scale.
__global__ void reduce_comb_ln(const float* __restrict__ P,
                               const float* __restrict__ bias,
                               float* __restrict__ h,
                               const float* __restrict__ g,
                               const float* __restrict__ b) {
    int n = blockIdx.x, t = threadIdx.x;
    __shared__ float red[8];
    __shared__ float stat;
    const size_t ND = (size_t)NPATCH * DMODEL;
    const int n2 = n >> 1, n4 = n >> 2;
    float v0 = h[n * DMODEL + t]       + bias[t];
    float v1 = h[n * DMODEL + t + 256] + bias[t + 256];
    v0 += P[0 * ND + (size_t)n  * DMODEL + t] + P[1 * ND + (size_t)n  * DMODEL + t];
    v1 += P[0 * ND + (size_t)n  * DMODEL + t + 256] + P[1 * ND + (size_t)n  * DMODEL + t + 256];
    v0 += P[2 * ND + (size_t)n2 * DMODEL + t] + P[3 * ND + (size_t)n2 * DMODEL + t];
    v1 += P[2 * ND + (size_t)n2 * DMODEL + t + 256] + P[3 * ND + (size_t)n2 * DMODEL + t + 256];
    v0 += P[4 * ND + (size_t)n4 * DMODEL + t] + P[5 * ND + (size_t)n4 * DMODEL + t];
    v1 += P[4 * ND + (size_t)n4 * DMODEL + t + 256] + P[5 * ND + (size_t)n4 * DMODEL + t + 256];

    float s = v0 + v1;
    #pragma unroll
    for (int o = 16; o; o >>= 1) s += __shfl_xor_sync(0xffffffffu, s, o);
    if ((t & 31) == 0) red[t >> 5] = s;
    __syncthreads();
    if (t < 32) {
        float x = (t < 8) ? red[t] : 0.f;
        #pragma unroll
        for (int o = 4; o; o >>= 1) x += __shfl_xor_sync(0xffffffffu, x, o);
        if (t == 0) stat = x / (float)DMODEL;
    }
    __syncthreads();
    float mean = stat;
    float dd0 = v0 - mean, dd1 = v1 - mean;

    __syncthreads();
    float vs = dd0 * dd0 + dd1 * dd1;
    #pragma unroll
    for (int o = 16; o; o >>= 1) vs += __shfl_xor_sync(0xffffffffu, vs, o);
    if ((t & 31) == 0) red[t >> 5] = vs;
    __syncthreads();
    if (t < 32) {
        float x = (t < 8) ? red[t] : 0.f;
        #pragma unroll
        for (int o = 4; o; o >>= 1) x += __shfl_xor_sync(0xffffffffu, x, o);
        if (t == 0) stat = rsqrtf(x / (float)DMODEL + LN_EPS);
    }
    __syncthreads();
    float rstd = stat;
    h[n * DMODEL + t]       = dd0 * rstd * g[t]       + b[t];
    h[n * DMODEL + t + 256] = dd1 * rstd * g[t + 256] + b[t + 256];
}

// h[n,:] = LayerNorm(h[n,:] + bias + sum_{s<S} part[s][n,:]) * g + b
__global__ void reduce_add_ln_kernel(const float* __restrict__ part, int S,
                                     const float* __restrict__ bias,
                                     float* __restrict__ h,
                                     const float* __restrict__ g,
                                     const float* __restrict__ b) {
    int n = blockIdx.x, t = threadIdx.x;
    __shared__ float red[8];
    __shared__ float stat;
    float v0 = h[n * DMODEL + t]       + bias[t];
    float v1 = h[n * DMODEL + t + 256] + bias[t + 256];
    for (int s = 0; s < S; s++) {
        v0 += part[(size_t)s * NPATCH * DMODEL + n * DMODEL + t];
        v1 += part[(size_t)s * NPATCH * DMODEL + n * DMODEL + t + 256];
    }

    float s = v0 + v1;
    #pragma unroll
    for (int o = 16; o; o >>= 1) s += __shfl_xor_sync(0xffffffffu, s, o);
    if ((t & 31) == 0) red[t >> 5] = s;
    __syncthreads();
    if (t < 32) {
        float x = (t < 8) ? red[t] : 0.f;
        #pragma unroll
        for (int o = 4; o; o >>= 1) x += __shfl_xor_sync(0xffffffffu, x, o);
        if (t == 0) stat = x / (float)DMODEL;
    }
    __syncthreads();
    float mean = stat;
    float dd0 = v0 - mean, dd1 = v1 - mean;

    __syncthreads();
    float vs = dd0 * dd0 + dd1 * dd1;
    #pragma unroll
    for (int o = 16; o; o >>= 1) vs += __shfl_xor_sync(0xffffffffu, vs, o);
    if ((t & 31) == 0) red[t >> 5] = vs;
    __syncthreads();
    if (t < 32) {
        float x = (t < 8) ? red[t] : 0.f;
        #pragma unroll
        for (int o = 4; o; o >>= 1) x += __shfl_xor_sync(0xffffffffu, x, o);
        if (t == 0) stat = rsqrtf(x / (float)DMODEL + LN_EPS);
    }
    __syncthreads();
    float rstd = stat;
    h[n * DMODEL + t]       = dd0 * rstd * g[t]       + b[t];
    h[n * DMODEL + t + 256] = dd1 * rstd * g[t + 256] + b[t + 256];
}

// fused global-mean-pool + head + softmax + broadcast
__global__ void head_kernel(const float* __restrict__ h, const float* __restrict__ W,
                            const float* __restrict__ b, float* __restrict__ out) {
    __shared__ float gs[DMODEL];
    __shared__ float red[8];
    __shared__ float stat;
    int t = threadIdx.x;  // 256
    {
        float s0 = 0.f, s1 = 0.f;
        for (int n = 0; n < NPATCH; n++) {
            s0 += h[n * DMODEL + t];
            s1 += h[n * DMODEL + t + 256];
        }
        gs[t] = s0 / (float)NPATCH;
        gs[t + 256] = s1 / (float)NPATCH;
    }
    __syncthreads();
    float acc = b[t];
    #pragma unroll 4
    for (int d = 0; d < DMODEL; d++) acc += gs[d] * W[d * NCLS + t];

    float m = acc;
    #pragma unroll
    for (int o = 16; o; o >>= 1) m = fmaxf(m, __shfl_xor_sync(0xffffffffu, m, o));
    if ((t & 31) == 0) red[t >> 5] = m;
    __syncthreads();
    if (t < 32) {
        float x = (t < 8) ? red[t] : -INFINITY;
        #pragma unroll
        for (int o = 4; o; o >>= 1) x = fmaxf(x, __shfl_xor_sync(0xffffffffu, x, o));
        if (t == 0) stat = x;
    }
    __syncthreads();
    float e = expf(acc - stat);
    __syncthreads();
    float s = e;
    #pragma unroll
    for (int o = 16; o; o >>= 1) s += __shfl_xor_sync(0xffffffffu, s, o);
    if ((t & 31) == 0) red[t >> 5] = s;
    __syncthreads();
    if (t < 32) {
        float x = (t < 8) ? red[t] : 0.f;
        #pragma unroll
        for (int o = 4; o; o >>= 1) x += __shfl_xor_sync(0xffffffffu, x, o);
        if (t == 0) stat = x;
    }
    __syncthreads();
    float p = e / stat;
    for (int bb = 0; bb < NBATCH; bb++) out[bb * NCLS + t] = p;
}

// ---------------- host launcher ----------------
extern "C" void kernel_launch(void* const* d_in, const int* in_sizes, int n_in,
                              void* d_out, int out_size) {
    const float* ln_in_b = (const float*)d_in[2];
    const float* patch_W = (const float*)d_in[3];
    const float* patch_b = (const float*)d_in[4];
    const float* pos_emb = (const float*)d_in[5];
    const float* Wq = (const float*)d_in[6];
    const float* bq = (const float*)d_in[7];
    const float* Wk = (const float*)d_in[8];
    const float* bk = (const float*)d_in[9];
    const float* Wv = (const float*)d_in[10];
    const float* bv = (const float*)d_in[11];
    const float* Wo = (const float*)d_in[12];
    const float* bo = (const float*)d_in[13];
    const float* Wc = (const float*)d_in[14];
    const float* bc = (const float*)d_in[15];
    const float* ln1_g = (const float*)d_in[16];
    const float* ln1_b = (const float*)d_in[17];
    const float* W1 = (const float*)d_in[18];
    const float* b1 = (const float*)d_in[19];
    const float* W2 = (const float*)d_in[20];
    const float* b2 = (const float*)d_in[21];
    const float* ln2_g = (const float*)d_in[22];
    const float* ln2_b = (const float*)d_in[23];
    const float* head_W = (const float*)d_in[24];
    const float* head_b = (const float*)d_in[25];
    float* out = (float*)d_out;

    static bool attrDone = false;
    if (!attrDone) {
        cudaFuncSetAttribute(gemm_std, cudaFuncAttributeMaxDynamicSharedMemorySize, SMEMB);
        cudaFuncSetAttribute(gemm_splitk, cudaFuncAttributeMaxDynamicSharedMemorySize, SMEMB);
        cudaFuncSetAttribute(gemm_qkv, cudaFuncAttributeMaxDynamicSharedMemorySize, SMEMB);
        cudaFuncSetAttribute(gemm_wo, cudaFuncAttributeMaxDynamicSharedMemorySize, SMEMB);
        cudaFuncSetAttribute(gemm_comb, cudaFuncAttributeMaxDynamicSharedMemorySize, SMEMB);
        attrDone = true;
    }

    float *hp, *pp, *qp, *kp, *vp, *op, *aop, *ffp, *partp, *csp, *qkvpp, *wopp;
    cudaGetSymbolAddress((void**)&hp,  d_h);
    cudaGetSymbolAddress((void**)&pp,  d_pool);
    cudaGetSymbolAddress((void**)&qp,  d_q);
    cudaGetSymbolAddress((void**)&kp,  d_k);
    cudaGetSymbolAddress((void**)&vp,  d_v);
    cudaGetSymbolAddress((void**)&op,  d_o);
    cudaGetSymbolAddress((void**)&aop, d_ao);
    cudaGetSymbolAddress((void**)&ffp, d_ff);
    cudaGetSymbolAddress((void**)&partp, d_part);
    cudaGetSymbolAddress((void**)&csp, d_cs);
    cudaGetSymbolAddress((void**)&qkvpp, d_qkvp);
    cudaGetSymbolAddress((void**)&wopp, d_wop);

    colsum_kernel<<<1, DMODEL>>>(patch_W, csp);
    init_h_kernel<<<NPATCH, DMODEL>>>(csp, ln_in_b, patch_b, pos_emb, hp);

    for (int l = 0; l < NLAYER; l++) {
        size_t wqkv = (size_t)l * 3 * DMODEL * QKVD;
        size_t bqkv = (size_t)l * 3 * QKVD;
        size_t wwo  = (size_t)l * 3 * QKVD * DMODEL;
        size_t bwo  = (size_t)l * 3 * DMODEL;

        pool_kernel<<<375, DMODEL>>>(hp, pp);
        gemm_qkv<<<dim3(3, 8, 18), 256, SMEMB>>>(hp, pp,
            Wq + wqkv, Wk + wqkv, Wv + wqkv, qkvpp);
        reduce_qkv<<<dim3(RTOT, 3), QKVD>>>(qkvpp, bq + bqkv, bk + bqkv, bv + bqkv,
                                            qp, kp, vp);
        attn_kernel<<<555, 256>>>(qp, kp, vp, op);
        gemm_wo<<<dim3(8, 8, 6), 256, SMEMB>>>(op, Wo + wwo, wopp);
        reduce_wo<<<RTOT, DMODEL>>>(wopp, bo + bwo, aop);

        // combine on pooled rows (identity: up(a)@Wc = up(a@Wc)), split-K 2 per scale
        gemm_comb<<<dim3(8, 8, 6), 256, SMEMB>>>(aop, Wc + (size_t)l * CATD * DMODEL,
                                                 partp);
        reduce_comb_ln<<<NPATCH, 256>>>(partp, bc + (size_t)l * DMODEL, hp,
                                        ln1_g + l * DMODEL, ln1_b + l * DMODEL);

        // FFN
        gemm_std<<<dim3(32, 8), 256, SMEMB>>>(hp, W1 + (size_t)l * DMODEL * FFD,
                                              b1 + (size_t)l * FFD, ffp,
                                              NPATCH, FFD, DMODEL, 1);
        gemm_splitk<<<dim3(8, 8, 8), 256, SMEMB>>>(ffp, W2 + (size_t)l * FFD * DMODEL,
                                                   partp, NPATCH, DMODEL, FFD, 256);
        reduce_add_ln_kernel<<<NPATCH, 256>>>(partp, 8, b2 + (size_t)l * DMODEL, hp,
                                              ln2_g + l * DMODEL, ln2_b + l * DMODEL);
    }

    head_kernel<<<1, NCLS>>>(hp, head_W, head_b, out);
}

// round 12
// speedup vs baseline: 1.3515x; 1.1177x over previous
#include <cuda_runtime.h>
#include <cuda_fp16.h>
#include <cstdint>
#include <math.h>

// ---------------- problem constants ----------------
#define NPATCH 500
#define DMODEL 512
#define KDIM   32
#define QKVD   160
#define CATD   1536
#define FFD    2048
#define NLAYER 6
#define NBATCH 32
#define NCLS   256
#define LN_EPS 1e-3f
#define RTOT 875     // rows: scale1 [0,500), scale2 [500,750), scale4 [750,875)

// fp16 GEMM: block 64x64, k-tile 32, 3 stages. smem halves:
//   A stage s: [s*2560 + m*40 + k]   (64 rows x 40-half stride)
//   B stage s: [7680 + s*2560 + n*40 + k]
#define AST 2560
#define BBASE 7680
#define SMEMB 30720   // bytes

// ---------------- scratch ----------------
__device__ float  d_h   [NPATCH * DMODEL];
__device__ __half d_h16 [NPATCH * DMODEL];
__device__ __half d_pool16[375 * DMODEL];
__device__ float  d_q   [RTOT * QKVD];
__device__ float  d_k   [RTOT * QKVD];
__device__ float  d_v   [RTOT * QKVD];
__device__ __half d_o16 [RTOT * QKVD];
__device__ __half d_ao16[RTOT * DMODEL];
__device__ __half d_ff16[NPATCH * FFD];
__device__ float  d_part[8 * NPATCH * DMODEL];
__device__ float  d_qkvp[6 * RTOT * QKVD];
__device__ float  d_wop [6 * RTOT * DMODEL];
__device__ float  d_cs  [DMODEL];
// fp16 transposed weights [batch][N][K]
__device__ __half d_Wq16[18 * QKVD * DMODEL];
__device__ __half d_Wk16[18 * QKVD * DMODEL];
__device__ __half d_Wv16[18 * QKVD * DMODEL];
__device__ __half d_Wo16[18 * DMODEL * QKVD];
__device__ __half d_Wc16[18 * DMODEL * DMODEL];
__device__ __half d_W116[6 * FFD * DMODEL];
__device__ __half d_W216[6 * DMODEL * FFD];

// ---------------- helpers ----------------
__device__ __forceinline__ uint32_t smem_u32(const void* p) {
    return (uint32_t)__cvta_generic_to_shared(p);
}
__device__ __forceinline__ void cp16(uint32_t dst, const void* src) {
    asm volatile("cp.async.cg.shared.global [%0], [%1], 16;\n" :: "r"(dst), "l"(src));
}
__device__ __forceinline__ void cp_commit() { asm volatile("cp.async.commit_group;\n"); }
__device__ __forceinline__ void ldsm4(uint32_t& d0, uint32_t& d1, uint32_t& d2, uint32_t& d3,
                                      uint32_t addr) {
    asm volatile("ldmatrix.sync.aligned.m8n8.x4.shared.b16 {%0,%1,%2,%3}, [%4];"
                 : "=r"(d0), "=r"(d1), "=r"(d2), "=r"(d3) : "r"(addr));
}
__device__ __forceinline__ void mma_f16(float* c, const uint32_t* a, uint32_t b0, uint32_t b1) {
    asm volatile(
        "mma.sync.aligned.m16n8k16.row.col.f32.f16.f16.f32 "
        "{%0,%1,%2,%3}, {%4,%5,%6,%7}, {%8,%9}, {%0,%1,%2,%3};"
        : "+f"(c[0]), "+f"(c[1]), "+f"(c[2]), "+f"(c[3])
        : "r"(a[0]), "r"(a[1]), "r"(a[2]), "r"(a[3]), "r"(b0), "r"(b1));
}
__device__ __forceinline__ float gelu_f(float x) {
    return 0.5f * x * (1.f + erff(x * 0.70710678118654752f));
}

// ---------------- transpose + fp32->fp16 convert: src[K][N] -> dst[N][K] ----
__global__ void transconv(const float* __restrict__ src, __half* __restrict__ dst,
                          int K, int N) {
    __shared__ float tile[32][33];
    const size_t b = blockIdx.z;
    src += b * (size_t)K * N;
    dst += b * (size_t)N * K;
    int n0 = blockIdx.x * 32, k0 = blockIdx.y * 32;
    int tx = threadIdx.x, ty = threadIdx.y;   // 32 x 8
    #pragma unroll
    for (int i = 0; i < 32; i += 8)
        tile[ty + i][tx] = src[(size_t)(k0 + ty + i) * N + n0 + tx];
    __syncthreads();
    #pragma unroll
    for (int i = 0; i < 32; i += 8)
        dst[(size_t)(n0 + ty + i) * K + k0 + tx] = __float2half_rn(tile[tx][ty + i]);
}

// ---------------- fp16 GEMM core (m16n8k16, ldmatrix A+B, 3-stage cp.async) ----
// 256 thr, 8 warps (2m x 4n), warp tile 32x16.
// A fp16 row-major [M][lda]; Bt fp16 n-major [N][ldb] (ldb = K of weight).
// kLen % 32 == 0, T >= 2. Writes fp32 C (ldc) or fp16 C16.
__device__ __forceinline__ void gemm_core(
    const __half* __restrict__ A, const __half* __restrict__ Bt,
    const float* __restrict__ bias, float* __restrict__ C, __half* __restrict__ C16,
    int M, int N, int lda, int ldb, int kOff, int kLen,
    int bM, int bN, int act, int addBias, int ldc)
{
    extern __shared__ __half smh[];
    const int tid = threadIdx.x, lane = tid & 31, warp = tid >> 5;
    const int wm = (warp & 1) << 5;      // 0,32
    const int wn = (warp >> 1) << 4;     // 0,16,32,48
    const int g = lane >> 2, t = lane & 3;
    const int lrow = (lane & 7) + ((lane >> 3) & 1) * 8;  // 0..15
    const int lk8 = (lane >> 4) << 3;                     // 0 or 8 (halves)

    // global fill: one 16B chunk per thread per operand per stage
    const int frow = tid >> 2;            // 0..63
    const int fch = (tid & 3) << 3;       // halves 0,8,16,24
    const __half* aSrc = A + (size_t)min(bM + frow, M - 1) * lda + kOff + fch;
    const __half* bSrc = Bt + (size_t)min(bN + frow, N - 1) * ldb + kOff + fch;
    uint32_t aD[3], bD[3];
    #pragma unroll
    for (int s = 0; s < 3; ++s) {
        aD[s] = smem_u32(&smh[s * AST + frow * 40 + fch]);
        bD[s] = smem_u32(&smh[BBASE + s * AST + frow * 40 + fch]);
    }

    const int T = kLen >> 5;
    #pragma unroll
    for (int p = 0; p < 2; ++p) {
        cp16(aD[p], aSrc + (p << 5));
        cp16(bD[p], bSrc + (p << 5));
        cp_commit();
    }

    const uint32_t smb = smem_u32(smh);
    uint32_t aFrag[2];
    #pragma unroll
    for (int i = 0; i < 2; ++i)
        aFrag[i] = ((wm + i * 16 + lrow) * 40 + lk8) * 2;
    const uint32_t bFrag = (BBASE + (wn + lrow) * 40 + lk8) * 2;

    float acc[2][2][4] = {};
    int stage = 0;
    for (int tt = 0; tt < T; ++tt) {
        if (tt + 1 < T) { asm volatile("cp.async.wait_group 1;\n"); }
        else            { asm volatile("cp.async.wait_group 0;\n"); }
        __syncthreads();

        if (tt + 2 < T) {
            const int ns = (stage + 2 >= 3) ? stage - 1 : stage + 2;
            const int ko = (tt + 2) << 5;
            cp16(aD[ns], aSrc + ko);
            cp16(bD[ns], bSrc + ko);
            cp_commit();
        }

        const uint32_t sb = smb + stage * (AST * 2);
        #pragma unroll
        for (int ks = 0; ks < 2; ++ks) {
            uint32_t af[2][4], bf[4];
            ldsm4(af[0][0], af[0][1], af[0][2], af[0][3], sb + aFrag[0] + ks * 32);
            ldsm4(af[1][0], af[1][1], af[1][2], af[1][3], sb + aFrag[1] + ks * 32);
            ldsm4(bf[0], bf[1], bf[2], bf[3], sb + bFrag + ks * 32);
            mma_f16(acc[0][0], af[0], bf[0], bf[2]);
            mma_f16(acc[0][1], af[0], bf[1], bf[3]);
            mma_f16(acc[1][0], af[1], bf[0], bf[2]);
            mma_f16(acc[1][1], af[1], bf[1], bf[3]);
        }
        stage = (stage + 1 >= 3) ? 0 : stage + 1;
    }

    // epilogue: acc[i][j] -> rows (r0, r0+8), cols (col, col+1); j covers n8 blocks 0,1
    #pragma unroll
    for (int i = 0; i < 2; ++i) {
        const int r0 = bM + wm + (i << 4) + g;
        const int r1 = r0 + 8;
        #pragma unroll
        for (int j = 0; j < 2; ++j) {
            const int col = bN + wn + (j << 3) + (t << 1);
            if (col >= N) continue;
            float b0v = 0.f, b1v = 0.f;
            if (addBias) {
                float2 bb = *(const float2*)(bias + col);
                b0v = bb.x; b1v = bb.y;
            }
            float c0 = acc[i][j][0] + b0v, c1 = acc[i][j][1] + b1v;
            float c2 = acc[i][j][2] + b0v, c3 = acc[i][j][3] + b1v;
            if (act) { c0 = gelu_f(c0); c1 = gelu_f(c1); c2 = gelu_f(c2); c3 = gelu_f(c3); }
            if (C16) {
                if (r0 < M) {
                    C16[(size_t)r0 * ldc + col] = __float2half_rn(c0);
                    C16[(size_t)r0 * ldc + col + 1] = __float2half_rn(c1);
                }
                if (r1 < M) {
                    C16[(size_t)r1 * ldc + col] = __float2half_rn(c2);
                    C16[(size_t)r1 * ldc + col + 1] = __float2half_rn(c3);
                }
            } else {
                if (r0 < M) *(float2*)(C + (size_t)r0 * ldc + col) = make_float2(c0, c1);
                if (r1 < M) *(float2*)(C + (size_t)r1 * ldc + col) = make_float2(c2, c3);
            }
        }
    }
}

// ---------------- GEMM wrappers ----------------
__constant__ int c_Ms[3] = {500, 250, 125};
__constant__ int c_ro[3] = {0, 500, 750};

// ffn1: h16 @ W1t -> gelu -> ff16
__global__ void __launch_bounds__(256) gemm_ffn1(
    const __half* __restrict__ h16, const __half* __restrict__ W1t,
    const float* __restrict__ b1, __half* __restrict__ ff16)
{
    int bM = blockIdx.y * 64;
    if (bM >= NPATCH) return;
    gemm_core(h16, W1t, b1, nullptr, ff16, NPATCH, FFD, DMODEL, DMODEL, 0, DMODEL,
              bM, blockIdx.x * 64, 1, 1, FFD);
}

// ffn2 split-K: z chunks of 256 over K=2048
__global__ void __launch_bounds__(256) gemm_ffn2(
    const __half* __restrict__ ff16, const __half* __restrict__ W2t,
    float* __restrict__ part)
{
    int bM = blockIdx.y * 64;
    if (bM >= NPATCH) return;
    int z = blockIdx.z;
    gemm_core(ff16, W2t, nullptr, part + (size_t)z * NPATCH * DMODEL, nullptr,
              NPATCH, DMODEL, FFD, FFD, z * 256, 256, bM, blockIdx.x * 64, 0, 0, DMODEL);
}

// qkv split-K: z = s*9 + si*3 + which ; kOff = s*256
__global__ void __launch_bounds__(256) gemm_qkv(
    const __half* __restrict__ h16, const __half* __restrict__ pool16,
    const __half* __restrict__ Wq, const __half* __restrict__ Wk,
    const __half* __restrict__ Wv, float* __restrict__ P)
{
    int z = blockIdx.z;
    int s = z / 9, rem = z - s * 9;
    int si = rem / 3, which = rem - si * 3;
    int M = c_Ms[si];
    int bM = blockIdx.y * 64;
    if (bM >= M) return;
    const __half* A = (si == 0) ? h16 : (pool16 + (si == 2 ? 250 * DMODEL : 0));
    const __half* W = (which == 0) ? Wq : (which == 1) ? Wk : Wv;
    float* Cb = P + ((size_t)(s * 3 + which) * RTOT + c_ro[si]) * QKVD;
    gemm_core(A, W + (size_t)si * QKVD * DMODEL, nullptr, Cb, nullptr,
              M, QKVD, DMODEL, DMODEL, s * 256, 256, bM, blockIdx.x * 64, 0, 0, QKVD);
}

// wo split-K: z = s*3 + si ; k split {0..96, 96..160}
__global__ void __launch_bounds__(256) gemm_wo(
    const __half* __restrict__ o16, const __half* __restrict__ Wot,
    float* __restrict__ P)
{
    int z = blockIdx.z;
    int s = z / 3, si = z - s * 3;
    int M = c_Ms[si];
    int bM = blockIdx.y * 64;
    if (bM >= M) return;
    int kOff = s ? 96 : 0;
    int kLen = s ? 64 : 96;
    float* Cb = P + ((size_t)(s * 3 + si) * RTOT + c_ro[si]) * DMODEL;
    gemm_core(o16 + (size_t)c_ro[si] * QKVD, Wot + (size_t)si * DMODEL * QKVD,
              nullptr, Cb, nullptr, M, DMODEL, QKVD, QKVD, kOff, kLen,
              bM, blockIdx.x * 64, 0, 0, DMODEL);
}

// combine on pooled rows: z = si*2 + s ; kOff = s*256
__global__ void __launch_bounds__(256) gemm_comb(
    const __half* __restrict__ ao16, const __half* __restrict__ Wct,
    float* __restrict__ P)
{
    int z = blockIdx.z;
    int si = z >> 1, s = z & 1;
    int M = c_Ms[si];
    int bM = blockIdx.y * 64;
    if (bM >= M) return;
    gemm_core(ao16 + (size_t)c_ro[si] * DMODEL, Wct + (size_t)si * DMODEL * DMODEL,
              nullptr, P + (size_t)z * NPATCH * DMODEL, nullptr,
              M, DMODEL, DMODEL, DMODEL, s * 256, 256, bM, blockIdx.x * 64, 0, 0, DMODEL);
}

// ---------------- small kernels ----------------
__global__ void colsum_kernel(const float* __restrict__ W, float* __restrict__ cs) {
    int d = threadIdx.x;
    float s = 0.f;
    #pragma unroll 4
    for (int p = 0; p < 100; p++) s += W[p * DMODEL + d];
    cs[d] = s;
}

__global__ void init_h_kernel(const float* __restrict__ cs, const float* __restrict__ ln_in_b,
                              const float* __restrict__ patch_b, const float* __restrict__ pos,
                              float* __restrict__ h, __half* __restrict__ h16) {
    int n = blockIdx.x, d = threadIdx.x;
    float v = ln_in_b[0] * cs[d] + patch_b[d] + pos[n * DMODEL + d];
    h[n * DMODEL + d] = v;
    h16[n * DMODEL + d] = __float2half_rn(v);
}

__global__ void pool_kernel(const float* __restrict__ h, __half* __restrict__ p16) {
    int i = blockIdx.x, d = threadIdx.x;
    float v;
    if (i < 250) {
        v = 0.5f * (h[(2 * i) * DMODEL + d] + h[(2 * i + 1) * DMODEL + d]);
    } else {
        int j = i - 250;
        v = 0.25f * (h[(4 * j) * DMODEL + d] + h[(4 * j + 1) * DMODEL + d] +
                     h[(4 * j + 2) * DMODEL + d] + h[(4 * j + 3) * DMODEL + d]);
    }
    p16[i * DMODEL + d] = __float2half_rn(v);
}

// q/k/v = P[s0]+P[s1]+bias ; grid (875,3) x 160 thr
__global__ void reduce_qkv(const float* __restrict__ P,
                           const float* __restrict__ bq, const float* __restrict__ bk,
                           const float* __restrict__ bv,
                           float* __restrict__ q, float* __restrict__ k,
                           float* __restrict__ v)
{
    int r = blockIdx.x, w = blockIdx.y, c = threadIdx.x;
    int si = (r < 500) ? 0 : (r < 750 ? 1 : 2);
    const float* bias = (w == 0) ? bq : (w == 1) ? bk : bv;
    float val = P[((size_t)(0 + w) * RTOT + r) * QKVD + c]
              + P[((size_t)(3 + w) * RTOT + r) * QKVD + c]
              + bias[si * QKVD + c];
    float* outp = (w == 0) ? q : (w == 1) ? k : v;
    outp[(size_t)r * QKVD + c] = val;
}

// ao16[r][d] = half(P[s0] + P[s1] + bo[si])
__global__ void reduce_wo(const float* __restrict__ P, const float* __restrict__ bo,
                          __half* __restrict__ ao16)
{
    int r = blockIdx.x, d = threadIdx.x;
    int si = (r < 500) ? 0 : (r < 750 ? 1 : 2);
    float v = P[((size_t)(0 + si) * RTOT + r) * DMODEL + d]
            + P[((size_t)(3 + si) * RTOT + r) * DMODEL + d]
            + bo[si * DMODEL + d];
    ao16[(size_t)r * DMODEL + d] = __float2half_rn(v);
}

// ---------------- attention (fp32 in, fp16 out) ----------------
__global__ void __launch_bounds__(256) attn_kernel(
    const float* __restrict__ q, const float* __restrict__ k,
    const float* __restrict__ v, __half* __restrict__ o16)
{
    __shared__ float Ks[32][34];
    __shared__ float Vs[32][34];
    __shared__ float OS[8][32][34];

    const int b = blockIdx.x;
    int Ns, ro, h, qg;
    if (b < 315)      { Ns = 500; ro = 0;   h = b / 63;  qg = b % 63; }
    else if (b < 475) { int c = b - 315; Ns = 250; ro = 500; h = c / 32; qg = c % 32; }
    else              { int c = b - 475; Ns = 125; ro = 750; h = c / 16; qg = c % 16; }

    const int wid = threadIdx.x >> 5;
    const int lane = threadIdx.x & 31;
    const int n = qg * 8 + wid;
    const bool valid = n < Ns;
    const int nq = valid ? n : (Ns - 1);
    const float scale = 0.1767766952966369f;  // 1/sqrt(32)

    float2 qr[16];
    {
        const float2* qp = (const float2*)(q + (size_t)(ro + nq) * QKVD + h * KDIM);
        #pragma unroll
        for (int i = 0; i < 16; i++) {
            float2 tq = qp[i];
            qr[i] = make_float2(tq.x * scale, tq.y * scale);
        }
    }

    float mmax = -INFINITY, ssum = 0.f;
    float oa[32];
    #pragma unroll
    for (int d = 0; d < 32; d++) oa[d] = 0.f;

    const int nt = (Ns + 31) >> 5;
    for (int tt = 0; tt < nt; tt++) {
        const int kt = tt << 5;
        {
            const int m = threadIdx.x >> 3;
            const int dq = (threadIdx.x & 7) << 2;
            const int row = min(kt + m, Ns - 1);
            const float4 kk = *(const float4*)(k + (size_t)(ro + row) * QKVD + h * KDIM + dq);
            const float4 vv = *(const float4*)(v + (size_t)(ro + row) * QKVD + h * KDIM + dq);
            *(float2*)&Ks[m][dq]     = make_float2(kk.x, kk.y);
            *(float2*)&Ks[m][dq + 2] = make_float2(kk.z, kk.w);
            *(float2*)&Vs[m][dq]     = make_float2(vv.x, vv.y);
            *(float2*)&Vs[m][dq + 2] = make_float2(vv.z, vv.w);
        }
        __syncthreads();

        float s0 = 0.f, s1 = 0.f;
        #pragma unroll
        for (int i = 0; i < 16; i++) {
            float2 kk = *(const float2*)&Ks[lane][2 * i];
            s0 = fmaf(qr[i].x, kk.x, s0);
            s1 = fmaf(qr[i].y, kk.y, s1);
        }
        float s = s0 + s1;
        if (kt + lane >= Ns) s = -INFINITY;

        float nm = fmaxf(mmax, s);
        float corr = __expf(mmax - nm);
        float p = __expf(s - nm);
        ssum = ssum * corr + p;
        #pragma unroll
        for (int i = 0; i < 16; i++) {
            float2 vv = *(const float2*)&Vs[lane][2 * i];
            oa[2 * i]     = oa[2 * i]     * corr + p * vv.x;
            oa[2 * i + 1] = oa[2 * i + 1] * corr + p * vv.y;
        }
        mmax = nm;
        __syncthreads();
    }

    float gm = mmax;
    #pragma unroll
    for (int off = 16; off; off >>= 1) gm = fmaxf(gm, __shfl_xor_sync(0xffffffffu, gm, off));
    float c = __expf(mmax - gm);
    float ss = ssum * c;
    #pragma unroll
    for (int off = 16; off; off >>= 1) ss += __shfl_xor_sync(0xffffffffu, ss, off);

    #pragma unroll
    for (int i = 0; i < 16; i++)
        *(float2*)&OS[wid][lane][2 * i] = make_float2(oa[2 * i] * c, oa[2 * i + 1] * c);
    __syncwarp();

    float accd = 0.f;
    #pragma unroll
    for (int m = 0; m < 32; m++) accd += OS[wid][m][lane];
    if (valid)
        o16[(size_t)(ro + n) * QKVD + h * KDIM + lane] = __float2half_rn(accd / ss);
}

// LN helpers: write fp32 h and fp16 h16
__device__ __forceinline__ void ln_finish(float v0, float v1, int n, int t,
                                          float* red, float* statp,
                                          float* __restrict__ h, __half* __restrict__ h16,
                                          const float* __restrict__ g,
                                          const float* __restrict__ b) {
    float s = v0 + v1;
    #pragma unroll
    for (int o = 16; o; o >>= 1) s += __shfl_xor_sync(0xffffffffu, s, o);
    if ((t & 31) == 0) red[t >> 5] = s;
    __syncthreads();
    if (t < 32) {
        float x = (t < 8) ? red[t] : 0.f;
        #pragma unroll
        for (int o = 4; o; o >>= 1) x += __shfl_xor_sync(0xffffffffu, x, o);
        if (t == 0) *statp = x / (float)DMODEL;
    }
    __syncthreads();
    float mean = *statp;
    float dd0 = v0 - mean, dd1 = v1 - mean;
    __syncthreads();
    float vs = dd0 * dd0 + dd1 * dd1;
    #pragma unroll
    for (int o = 16; o; o >>= 1) vs += __shfl_xor_sync(0xffffffffu, vs, o);
    if ((t & 31) == 0) red[t >> 5] = vs;
    __syncthreads();
    if (t < 32) {
        float x = (t < 8) ? red[t] : 0.f;
        #pragma unroll
        for (int o = 4; o; o >>= 1) x += __shfl_xor_sync(0xffffffffu, x, o);
        if (t == 0) *statp = rsqrtf(x / (float)DMODEL + LN_EPS);
    }
    __syncthreads();
    float rstd = *statp;
    float o0 = dd0 * rstd * g[t] + b[t];
    float o1 = dd1 * rstd * g[t + 256] + b[t + 256];
    h[n * DMODEL + t] = o0;
    h[n * DMODEL + t + 256] = o1;
    h16[n * DMODEL + t] = __float2half_rn(o0);
    h16[n * DMODEL + t + 256] = __float2half_rn(o1);
}

// comb partials (upsampled) + residual + LN
__global__ void reduce_comb_ln(const float* __restrict__ P,
                               const float* __restrict__ bias,
                               float* __restrict__ h, __half* __restrict__ h16,
                               const float* __restrict__ g,
                               const float* __restrict__ b) {
    int n = blockIdx.x, t = threadIdx.x;
    __shared__ float red[8];
    __shared__ float stat;
    const size_t ND = (size_t)NPATCH * DMODEL;
    const int n2 = n >> 1, n4 = n >> 2;
    float v0 = h[n * DMODEL + t]       + bias[t];
    float v1 = h[n * DMODEL + t + 256] + bias[t + 256];
    v0 += P[0 * ND + (size_t)n  * DMODEL + t] + P[1 * ND + (size_t)n  * DMODEL + t];
    v1 += P[0 * ND + (size_t)n  * DMODEL + t + 256] + P[1 * ND + (size_t)n  * DMODEL + t + 256];
    v0 += P[2 * ND + (size_t)n2 * DMODEL + t] + P[3 * ND + (size_t)n2 * DMODEL + t];
    v1 += P[2 * ND + (size_t)n2 * DMODEL + t + 256] + P[3 * ND + (size_t)n2 * DMODEL + t + 256];
    v0 += P[4 * ND + (size_t)n4 * DMODEL + t] + P[5 * ND + (size_t)n4 * DMODEL + t];
    v1 += P[4 * ND + (size_t)n4 * DMODEL + t + 256] + P[5 * ND + (size_t)n4 * DMODEL + t + 256];
    ln_finish(v0, v1, n, t, red, &stat, h, h16, g, b);
}

// ffn2 partials + residual + LN
__global__ void reduce_add_ln(const float* __restrict__ part, int S,
                              const float* __restrict__ bias,
                              float* __restrict__ h, __half* __restrict__ h16,
                              const float* __restrict__ g,
                              const float* __restrict__ b) {
    int n = blockIdx.x, t = threadIdx.x;
    __shared__ float red[8];
    __shared__ float stat;
    float v0 = h[n * DMODEL + t]       + bias[t];
    float v1 = h[n * DMODEL + t + 256] + bias[t + 256];
    for (int s = 0; s < S; s++) {
        v0 += part[(size_t)s * NPATCH * DMODEL + n * DMODEL + t];
        v1 += part[(size_t)s * NPATCH * DMODEL + n * DMODEL + t + 256];
    }
    ln_finish(v0, v1, n, t, red, &stat, h, h16, g, b);
}

// fused global-mean-pool + head + softmax + broadcast
__global__ void head_kernel(const float* __restrict__ h, const float* __restrict__ W,
                            const float* __restrict__ b, float* __restrict__ out) {
    __shared__ float gs[DMODEL];
    __shared__ float red[8];
    __shared__ float stat;
    int t = threadIdx.x;  // 256
    {
        float s0 = 0.f, s1 = 0.f;
        for (int n = 0; n < NPATCH; n++) {
            s0 += h[n * DMODEL + t];
            s1 += h[n * DMODEL + t + 256];
        }
        gs[t] = s0 / (float)NPATCH;
        gs[t + 256] = s1 / (float)NPATCH;
    }
    __syncthreads();
    float acc = b[t];
    #pragma unroll 4
    for (int d = 0; d < DMODEL; d++) acc += gs[d] * W[d * NCLS + t];

    float m = acc;
    #pragma unroll
    for (int o = 16; o; o >>= 1) m = fmaxf(m, __shfl_xor_sync(0xffffffffu, m, o));
    if ((t & 31) == 0) red[t >> 5] = m;
    __syncthreads();
    if (t < 32) {
        float x = (t < 8) ? red[t] : -INFINITY;
        #pragma unroll
        for (int o = 4; o; o >>= 1) x = fmaxf(x, __shfl_xor_sync(0xffffffffu, x, o));
        if (t == 0) stat = x;
    }
    __syncthreads();
    float e = expf(acc - stat);
    __syncthreads();
    float s = e;
    #pragma unroll
    for (int o = 16; o; o >>= 1) s += __shfl_xor_sync(0xffffffffu, s, o);
    if ((t & 31) == 0) red[t >> 5] = s;
    __syncthreads();
    if (t < 32) {
        float x = (t < 8) ? red[t] : 0.f;
        #pragma unroll
        for (int o = 4; o; o >>= 1) x += __shfl_xor_sync(0xffffffffu, x, o);
        if (t == 0) stat = x;
    }
    __syncthreads();
    float p = e / stat;
    for (int bb = 0; bb < NBATCH; bb++) out[bb * NCLS + t] = p;
}

// ---------------- host launcher ----------------
extern "C" void kernel_launch(void* const* d_in, const int* in_sizes, int n_in,
                              void* d_out, int out_size) {
    const float* ln_in_b = (const float*)d_in[2];
    const float* patch_W = (const float*)d_in[3];
    const float* patch_b = (const float*)d_in[4];
    const float* pos_emb = (const float*)d_in[5];
    const float* Wq = (const float*)d_in[6];
    const float* bq = (const float*)d_in[7];
    const float* Wk = (const float*)d_in[8];
    const float* bk = (const float*)d_in[9];
    const float* Wv = (const float*)d_in[10];
    const float* bv = (const float*)d_in[11];
    const float* Wo = (const float*)d_in[12];
    const float* bo = (const float*)d_in[13];
    const float* Wc = (const float*)d_in[14];
    const float* bc = (const float*)d_in[15];
    const float* ln1_g = (const float*)d_in[16];
    const float* ln1_b = (const float*)d_in[17];
    const float* W1 = (const float*)d_in[18];
    const float* b1 = (const float*)d_in[19];
    const float* W2 = (const float*)d_in[20];
    const float* b2 = (const float*)d_in[21];
    const float* ln2_g = (const float*)d_in[22];
    const float* ln2_b = (const float*)d_in[23];
    const float* head_W = (const float*)d_in[24];
    const float* head_b = (const float*)d_in[25];
    float* out = (float*)d_out;

    float *hp, *qp, *kp, *vp, *partp, *csp, *qkvpp, *wopp;
    __half *h16p, *pool16p, *o16p, *ao16p, *ff16p;
    __half *wq16, *wk16, *wv16, *wo16, *wc16, *w116, *w216;
    cudaGetSymbolAddress((void**)&hp,  d_h);
    cudaGetSymbolAddress((void**)&h16p, d_h16);
    cudaGetSymbolAddress((void**)&pool16p, d_pool16);
    cudaGetSymbolAddress((void**)&qp,  d_q);
    cudaGetSymbolAddress((void**)&kp,  d_k);
    cudaGetSymbolAddress((void**)&vp,  d_v);
    cudaGetSymbolAddress((void**)&o16p, d_o16);
    cudaGetSymbolAddress((void**)&ao16p, d_ao16);
    cudaGetSymbolAddress((void**)&ff16p, d_ff16);
    cudaGetSymbolAddress((void**)&partp, d_part);
    cudaGetSymbolAddress((void**)&csp, d_cs);
    cudaGetSymbolAddress((void**)&qkvpp, d_qkvp);
    cudaGetSymbolAddress((void**)&wopp, d_wop);
    cudaGetSymbolAddress((void**)&wq16, d_Wq16);
    cudaGetSymbolAddress((void**)&wk16, d_Wk16);
    cudaGetSymbolAddress((void**)&wv16, d_Wv16);
    cudaGetSymbolAddress((void**)&wo16, d_Wo16);
    cudaGetSymbolAddress((void**)&wc16, d_Wc16);
    cudaGetSymbolAddress((void**)&w116, d_W116);
    cudaGetSymbolAddress((void**)&w216, d_W216);

    dim3 tb(32, 8);
    // weight transpose+convert (fp32 [K][N] -> fp16 [N][K])
    transconv<<<dim3(QKVD / 32, DMODEL / 32, 18), tb>>>(Wq, wq16, DMODEL, QKVD);
    transconv<<<dim3(QKVD / 32, DMODEL / 32, 18), tb>>>(Wk, wk16, DMODEL, QKVD);
    transconv<<<dim3(QKVD / 32, DMODEL / 32, 18), tb>>>(Wv, wv16, DMODEL, QKVD);
    transconv<<<dim3(DMODEL / 32, QKVD / 32, 18), tb>>>(Wo, wo16, QKVD, DMODEL);
    transconv<<<dim3(DMODEL / 32, DMODEL / 32, 18), tb>>>(Wc, wc16, DMODEL, DMODEL);
    transconv<<<dim3(FFD / 32, DMODEL / 32, 6), tb>>>(W1, w116, DMODEL, FFD);
    transconv<<<dim3(DMODEL / 32, FFD / 32, 6), tb>>>(W2, w216, FFD, DMODEL);

    colsum_kernel<<<1, DMODEL>>>(patch_W, csp);
    init_h_kernel<<<NPATCH, DMODEL>>>(csp, ln_in_b, patch_b, pos_emb, hp, h16p);

    for (int l = 0; l < NLAYER; l++) {
        size_t bqkv = (size_t)l * 3 * QKVD;
        size_t bwo  = (size_t)l * 3 * DMODEL;

        pool_kernel<<<375, DMODEL>>>(hp, pool16p);
        gemm_qkv<<<dim3(3, 8, 18), 256, SMEMB>>>(h16p, pool16p,
            wq16 + (size_t)l * 3 * QKVD * DMODEL,
            wk16 + (size_t)l * 3 * QKVD * DMODEL,
            wv16 + (size_t)l * 3 * QKVD * DMODEL, qkvpp);
        reduce_qkv<<<dim3(RTOT, 3), QKVD>>>(qkvpp, bq + bqkv, bk + bqkv, bv + bqkv,
                                            qp, kp, vp);
        attn_kernel<<<555, 256>>>(qp, kp, vp, o16p);
        gemm_wo<<<dim3(8, 8, 6), 256, SMEMB>>>(o16p,
            wo16 + (size_t)l * 3 * DMODEL * QKVD, wopp);
        reduce_wo<<<RTOT, DMODEL>>>(wopp, bo + bwo, ao16p);

        gemm_comb<<<dim3(8, 8, 6), 256, SMEMB>>>(ao16p,
            wc16 + (size_t)l * 3 * DMODEL * DMODEL, partp);
        reduce_comb_ln<<<NPATCH, 256>>>(partp, bc + (size_t)l * DMODEL, hp, h16p,
                                        ln1_g + l * DMODEL, ln1_b + l * DMODEL);

        gemm_ffn1<<<dim3(32, 8), 256, SMEMB>>>(h16p,
            w116 + (size_t)l * FFD * DMODEL, b1 + (size_t)l * FFD, ff16p);
        gemm_ffn2<<<dim3(8, 8, 8), 256, SMEMB>>>(ff16p,
            w216 + (size_t)l * DMODEL * FFD, partp);
        reduce_add_ln<<<NPATCH, 256>>>(partp, 8, b2 + (size_t)l * DMODEL, hp, h16p,
                                       ln2_g + l * DMODEL, ln2_b + l * DMODEL);
    }

    head_kernel<<<1, NCLS>>>(hp, head_W, head_b, out);
}

// round 13
// speedup vs baseline: 1.3971x; 1.0338x over previous
#include <cuda_runtime.h>
#include <cuda_fp16.h>
#include <cstdint>
#include <math.h>

// ---------------- problem constants ----------------
#define NPATCH 500
#define DMODEL 512
#define KDIM   32
#define QKVD   160
#define CATD   1536
#define FFD    2048
#define NLAYER 6
#define NBATCH 32
#define NCLS   256
#define LN_EPS 1e-3f
#define RTOT 875     // rows: scale1 [0,500), scale2 [500,750), scale4 [750,875)

// fp16 GEMM: block 64x64, k-tile 32, 3 stages. smem halves:
#define AST 2560
#define BBASE 7680
#define SMEMB 30720   // bytes

// ---------------- scratch ----------------
__device__ float  d_h   [NPATCH * DMODEL];
__device__ __half d_h16 [NPATCH * DMODEL];
__device__ __half d_pool16[375 * DMODEL];
__device__ float  d_q   [RTOT * QKVD];
__device__ float  d_k   [RTOT * QKVD];
__device__ float  d_v   [RTOT * QKVD];
__device__ __half d_o16 [RTOT * QKVD];
__device__ __half d_ao16[RTOT * DMODEL];
__device__ __half d_ff16[NPATCH * FFD];
__device__ float  d_part[4 * NPATCH * DMODEL];
__device__ float  d_cs  [DMODEL];
// fp16 transposed weights [batch][N][K]
__device__ __half d_Wq16[18 * QKVD * DMODEL];
__device__ __half d_Wk16[18 * QKVD * DMODEL];
__device__ __half d_Wv16[18 * QKVD * DMODEL];
__device__ __half d_Wo16[18 * DMODEL * QKVD];
__device__ __half d_Wc16[18 * DMODEL * DMODEL];
__device__ __half d_W116[6 * FFD * DMODEL];
__device__ __half d_W216[6 * DMODEL * FFD];

// ---------------- helpers ----------------
__device__ __forceinline__ uint32_t smem_u32(const void* p) {
    return (uint32_t)__cvta_generic_to_shared(p);
}
__device__ __forceinline__ void cp16(uint32_t dst, const void* src) {
    asm volatile("cp.async.cg.shared.global [%0], [%1], 16;\n" :: "r"(dst), "l"(src));
}
__device__ __forceinline__ void cp_commit() { asm volatile("cp.async.commit_group;\n"); }
__device__ __forceinline__ void ldsm4(uint32_t& d0, uint32_t& d1, uint32_t& d2, uint32_t& d3,
                                      uint32_t addr) {
    asm volatile("ldmatrix.sync.aligned.m8n8.x4.shared.b16 {%0,%1,%2,%3}, [%4];"
                 : "=r"(d0), "=r"(d1), "=r"(d2), "=r"(d3) : "r"(addr));
}
__device__ __forceinline__ void mma_f16(float* c, const uint32_t* a, uint32_t b0, uint32_t b1) {
    asm volatile(
        "mma.sync.aligned.m16n8k16.row.col.f32.f16.f16.f32 "
        "{%0,%1,%2,%3}, {%4,%5,%6,%7}, {%8,%9}, {%0,%1,%2,%3};"
        : "+f"(c[0]), "+f"(c[1]), "+f"(c[2]), "+f"(c[3])
        : "r"(a[0]), "r"(a[1]), "r"(a[2]), "r"(a[3]), "r"(b0), "r"(b1));
}
__device__ __forceinline__ float gelu_f(float x) {
    return 0.5f * x * (1.f + erff(x * 0.70710678118654752f));
}

// ---------------- transpose + fp32->fp16 convert: src[K][N] -> dst[N][K] ----
__global__ void transconv(const float* __restrict__ src, __half* __restrict__ dst,
                          int K, int N) {
    __shared__ float tile[32][33];
    const size_t b = blockIdx.z;
    src += b * (size_t)K * N;
    dst += b * (size_t)N * K;
    int n0 = blockIdx.x * 32, k0 = blockIdx.y * 32;
    int tx = threadIdx.x, ty = threadIdx.y;   // 32 x 8
    #pragma unroll
    for (int i = 0; i < 32; i += 8)
        tile[ty + i][tx] = src[(size_t)(k0 + ty + i) * N + n0 + tx];
    __syncthreads();
    #pragma unroll
    for (int i = 0; i < 32; i += 8)
        dst[(size_t)(n0 + ty + i) * K + k0 + tx] = __float2half_rn(tile[tx][ty + i]);
}

// ---------------- fp16 GEMM core (m16n8k16, ldmatrix A+B, 3-stage cp.async) ----
// 256 thr, 8 warps (2m x 4n), warp tile 32x16.
// A fp16 row-major [M][lda]; Bt fp16 n-major [N][ldb].
// kLen % 32 == 0, T >= 2. Writes fp32 C (ldc) or fp16 C16 (ldc).
__device__ __forceinline__ void gemm_core(
    const __half* __restrict__ A, const __half* __restrict__ Bt,
    const float* __restrict__ bias, float* __restrict__ C, __half* __restrict__ C16,
    int M, int N, int lda, int ldb, int kOff, int kLen,
    int bM, int bN, int act, int addBias, int ldc)
{
    extern __shared__ __half smh[];
    const int tid = threadIdx.x, lane = tid & 31, warp = tid >> 5;
    const int wm = (warp & 1) << 5;      // 0,32
    const int wn = (warp >> 1) << 4;     // 0,16,32,48
    const int g = lane >> 2, t = lane & 3;
    const int lrow = (lane & 7) + ((lane >> 3) & 1) * 8;  // 0..15
    const int lk8 = (lane >> 4) << 3;                     // 0 or 8 (halves)

    const int frow = tid >> 2;            // 0..63
    const int fch = (tid & 3) << 3;       // halves 0,8,16,24
    const __half* aSrc = A + (size_t)min(bM + frow, M - 1) * lda + kOff + fch;
    const __half* bSrc = Bt + (size_t)min(bN + frow, N - 1) * ldb + kOff + fch;
    uint32_t aD[3], bD[3];
    #pragma unroll
    for (int s = 0; s < 3; ++s) {
        aD[s] = smem_u32(&smh[s * AST + frow * 40 + fch]);
        bD[s] = smem_u32(&smh[BBASE + s * AST + frow * 40 + fch]);
    }

    const int T = kLen >> 5;
    #pragma unroll
    for (int p = 0; p < 2; ++p) {
        cp16(aD[p], aSrc + (p << 5));
        cp16(bD[p], bSrc + (p << 5));
        cp_commit();
    }

    const uint32_t smb = smem_u32(smh);
    uint32_t aFrag[2];
    #pragma unroll
    for (int i = 0; i < 2; ++i)
        aFrag[i] = ((wm + i * 16 + lrow) * 40 + lk8) * 2;
    const uint32_t bFrag = (BBASE + (wn + lrow) * 40 + lk8) * 2;

    float acc[2][2][4] = {};
    int stage = 0;
    for (int tt = 0; tt < T; ++tt) {
        if (tt + 1 < T) { asm volatile("cp.async.wait_group 1;\n"); }
        else            { asm volatile("cp.async.wait_group 0;\n"); }
        __syncthreads();

        if (tt + 2 < T) {
            const int ns = (stage + 2 >= 3) ? stage - 1 : stage + 2;
            const int ko = (tt + 2) << 5;
            cp16(aD[ns], aSrc + ko);
            cp16(bD[ns], bSrc + ko);
            cp_commit();
        }

        const uint32_t sb = smb + stage * (AST * 2);
        #pragma unroll
        for (int ks = 0; ks < 2; ++ks) {
            uint32_t af[2][4], bf[4];
            ldsm4(af[0][0], af[0][1], af[0][2], af[0][3], sb + aFrag[0] + ks * 32);
            ldsm4(af[1][0], af[1][1], af[1][2], af[1][3], sb + aFrag[1] + ks * 32);
            ldsm4(bf[0], bf[1], bf[2], bf[3], sb + bFrag + ks * 32);
            mma_f16(acc[0][0], af[0], bf[0], bf[2]);
            mma_f16(acc[0][1], af[0], bf[1], bf[3]);
            mma_f16(acc[1][0], af[1], bf[0], bf[2]);
            mma_f16(acc[1][1], af[1], bf[1], bf[3]);
        }
        stage = (stage + 1 >= 3) ? 0 : stage + 1;
    }

    #pragma unroll
    for (int i = 0; i < 2; ++i) {
        const int r0 = bM + wm + (i << 4) + g;
        const int r1 = r0 + 8;
        #pragma unroll
        for (int j = 0; j < 2; ++j) {
            const int col = bN + wn + (j << 3) + (t << 1);
            if (col >= N) continue;
            float b0v = 0.f, b1v = 0.f;
            if (addBias) {
                float2 bb = *(const float2*)(bias + col);
                b0v = bb.x; b1v = bb.y;
            }
            float c0 = acc[i][j][0] + b0v, c1 = acc[i][j][1] + b1v;
            float c2 = acc[i][j][2] + b0v, c3 = acc[i][j][3] + b1v;
            if (act) { c0 = gelu_f(c0); c1 = gelu_f(c1); c2 = gelu_f(c2); c3 = gelu_f(c3); }
            if (C16) {
                if (r0 < M) {
                    C16[(size_t)r0 * ldc + col] = __float2half_rn(c0);
                    C16[(size_t)r0 * ldc + col + 1] = __float2half_rn(c1);
                }
                if (r1 < M) {
                    C16[(size_t)r1 * ldc + col] = __float2half_rn(c2);
                    C16[(size_t)r1 * ldc + col + 1] = __float2half_rn(c3);
                }
            } else {
                if (r0 < M) *(float2*)(C + (size_t)r0 * ldc + col) = make_float2(c0, c1);
                if (r1 < M) *(float2*)(C + (size_t)r1 * ldc + col) = make_float2(c2, c3);
            }
        }
    }
}

// ---------------- GEMM wrappers ----------------
__constant__ int c_Ms[3] = {500, 250, 125};
__constant__ int c_ro[3] = {0, 500, 750};

// ffn1: h16 @ W1t + b1 -> gelu -> ff16
__global__ void __launch_bounds__(256) gemm_ffn1(
    const __half* __restrict__ h16, const __half* __restrict__ W1t,
    const float* __restrict__ b1, __half* __restrict__ ff16)
{
    int bM = blockIdx.y * 64;
    if (bM >= NPATCH) return;
    gemm_core(h16, W1t, b1, nullptr, ff16, NPATCH, FFD, DMODEL, DMODEL, 0, DMODEL,
              bM, blockIdx.x * 64, 1, 1, FFD);
}

// ffn2 split-K 4: z chunks of 512 over K=2048
__global__ void __launch_bounds__(256) gemm_ffn2(
    const __half* __restrict__ ff16, const __half* __restrict__ W2t,
    float* __restrict__ part)
{
    int bM = blockIdx.y * 64;
    if (bM >= NPATCH) return;
    int z = blockIdx.z;
    gemm_core(ff16, W2t, nullptr, part + (size_t)z * NPATCH * DMODEL, nullptr,
              NPATCH, DMODEL, FFD, FFD, z * 512, 512, bM, blockIdx.x * 64, 0, 0, DMODEL);
}

// qkv full-K with fused bias: z = si*3 + which, writes fp32 q/k/v directly
__global__ void __launch_bounds__(256) gemm_qkv(
    const __half* __restrict__ h16, const __half* __restrict__ pool16,
    const __half* __restrict__ Wq, const __half* __restrict__ Wk,
    const __half* __restrict__ Wv,
    const float* __restrict__ bq, const float* __restrict__ bk,
    const float* __restrict__ bv,
    float* __restrict__ q, float* __restrict__ k, float* __restrict__ v)
{
    int z = blockIdx.z;
    int si = z / 3, which = z - si * 3;
    int M = c_Ms[si];
    int bM = blockIdx.y * 64;
    if (bM >= M) return;
    const __half* A = (si == 0) ? h16 : (pool16 + (si == 2 ? 250 * DMODEL : 0));
    const __half* W = (which == 0) ? Wq : (which == 1) ? Wk : Wv;
    const float* bb = (which == 0) ? bq : (which == 1) ? bk : bv;
    float* Cb = (which == 0) ? q : (which == 1) ? k : v;
    gemm_core(A, W + (size_t)si * QKVD * DMODEL, bb + (size_t)si * QKVD,
              Cb + (size_t)c_ro[si] * QKVD, nullptr,
              M, QKVD, DMODEL, DMODEL, 0, DMODEL, bM, blockIdx.x * 64, 0, 1, QKVD);
}

// wo full-K (160) with fused bias, fp16 out: z = si
__global__ void __launch_bounds__(256) gemm_wo(
    const __half* __restrict__ o16, const __half* __restrict__ Wot,
    const float* __restrict__ bo, __half* __restrict__ ao16)
{
    int si = blockIdx.z;
    int M = c_Ms[si];
    int bM = blockIdx.y * 64;
    if (bM >= M) return;
    gemm_core(o16 + (size_t)c_ro[si] * QKVD, Wot + (size_t)si * DMODEL * QKVD,
              bo + (size_t)si * DMODEL, nullptr, ao16 + (size_t)c_ro[si] * DMODEL,
              M, DMODEL, QKVD, QKVD, 0, QKVD, bM, blockIdx.x * 64, 0, 1, DMODEL);
}

// combine on pooled rows, full K=512: z = si ; partial P[si]
__global__ void __launch_bounds__(256) gemm_comb(
    const __half* __restrict__ ao16, const __half* __restrict__ Wct,
    float* __restrict__ P)
{
    int si = blockIdx.z;
    int M = c_Ms[si];
    int bM = blockIdx.y * 64;
    if (bM >= M) return;
    gemm_core(ao16 + (size_t)c_ro[si] * DMODEL, Wct + (size_t)si * DMODEL * DMODEL,
              nullptr, P + (size_t)si * NPATCH * DMODEL, nullptr,
              M, DMODEL, DMODEL, DMODEL, 0, DMODEL, bM, blockIdx.x * 64, 0, 0, DMODEL);
}

// ---------------- small kernels ----------------
__global__ void colsum_kernel(const float* __restrict__ W, float* __restrict__ cs) {
    int d = threadIdx.x;
    float s = 0.f;
    #pragma unroll 4
    for (int p = 0; p < 100; p++) s += W[p * DMODEL + d];
    cs[d] = s;
}

__global__ void init_h_kernel(const float* __restrict__ cs, const float* __restrict__ ln_in_b,
                              const float* __restrict__ patch_b, const float* __restrict__ pos,
                              float* __restrict__ h, __half* __restrict__ h16) {
    int n = blockIdx.x, d = threadIdx.x;
    float v = ln_in_b[0] * cs[d] + patch_b[d] + pos[n * DMODEL + d];
    h[n * DMODEL + d] = v;
    h16[n * DMODEL + d] = __float2half_rn(v);
}

__global__ void pool_kernel(const float* __restrict__ h, __half* __restrict__ p16) {
    int i = blockIdx.x, d = threadIdx.x;
    float v;
    if (i < 250) {
        v = 0.5f * (h[(2 * i) * DMODEL + d] + h[(2 * i + 1) * DMODEL + d]);
    } else {
        int j = i - 250;
        v = 0.25f * (h[(4 * j) * DMODEL + d] + h[(4 * j + 1) * DMODEL + d] +
                     h[(4 * j + 2) * DMODEL + d] + h[(4 * j + 3) * DMODEL + d]);
    }
    p16[i * DMODEL + d] = __float2half_rn(v);
}

// ---------------- attention (fp32 in, fp16 out) ----------------
__global__ void __launch_bounds__(256) attn_kernel(
    const float* __restrict__ q, const float* __restrict__ k,
    const float* __restrict__ v, __half* __restrict__ o16)
{
    __shared__ float Ks[32][34];
    __shared__ float Vs[32][34];
    __shared__ float OS[8][32][34];

    const int b = blockIdx.x;
    int Ns, ro, h, qg;
    if (b < 315)      { Ns = 500; ro = 0;   h = b / 63;  qg = b % 63; }
    else if (b < 475) { int c = b - 315; Ns = 250; ro = 500; h = c / 32; qg = c % 32; }
    else              { int c = b - 475; Ns = 125; ro = 750; h = c / 16; qg = c % 16; }

    const int wid = threadIdx.x >> 5;
    const int lane = threadIdx.x & 31;
    const int n = qg * 8 + wid;
    const bool valid = n < Ns;
    const int nq = valid ? n : (Ns - 1);
    const float scale = 0.1767766952966369f;  // 1/sqrt(32)

    float2 qr[16];
    {
        const float2* qp = (const float2*)(q + (size_t)(ro + nq) * QKVD + h * KDIM);
        #pragma unroll
        for (int i = 0; i < 16; i++) {
            float2 tq = qp[i];
            qr[i] = make_float2(tq.x * scale, tq.y * scale);
        }
    }

    float mmax = -INFINITY, ssum = 0.f;
    float oa[32];
    #pragma unroll
    for (int d = 0; d < 32; d++) oa[d] = 0.f;

    const int nt = (Ns + 31) >> 5;
    for (int tt = 0; tt < nt; tt++) {
        const int kt = tt << 5;
        {
            const int m = threadIdx.x >> 3;
            const int dq = (threadIdx.x & 7) << 2;
            const int row = min(kt + m, Ns - 1);
            const float4 kk = *(const float4*)(k + (size_t)(ro + row) * QKVD + h * KDIM + dq);
            const float4 vv = *(const float4*)(v + (size_t)(ro + row) * QKVD + h * KDIM + dq);
            *(float2*)&Ks[m][dq]     = make_float2(kk.x, kk.y);
            *(float2*)&Ks[m][dq + 2] = make_float2(kk.z, kk.w);
            *(float2*)&Vs[m][dq]     = make_float2(vv.x, vv.y);
            *(float2*)&Vs[m][dq + 2] = make_float2(vv.z, vv.w);
        }
        __syncthreads();

        float s0 = 0.f, s1 = 0.f;
        #pragma unroll
        for (int i = 0; i < 16; i++) {
            float2 kk = *(const float2*)&Ks[lane][2 * i];
            s0 = fmaf(qr[i].x, kk.x, s0);
            s1 = fmaf(qr[i].y, kk.y, s1);
        }
        float s = s0 + s1;
        if (kt + lane >= Ns) s = -INFINITY;

        float nm = fmaxf(mmax, s);
        float corr = __expf(mmax - nm);
        float p = __expf(s - nm);
        ssum = ssum * corr + p;
        #pragma unroll
        for (int i = 0; i < 16; i++) {
            float2 vv = *(const float2*)&Vs[lane][2 * i];
            oa[2 * i]     = oa[2 * i]     * corr + p * vv.x;
            oa[2 * i + 1] = oa[2 * i + 1] * corr + p * vv.y;
        }
        mmax = nm;
        __syncthreads();
    }

    float gm = mmax;
    #pragma unroll
    for (int off = 16; off; off >>= 1) gm = fmaxf(gm, __shfl_xor_sync(0xffffffffu, gm, off));
    float c = __expf(mmax - gm);
    float ss = ssum * c;
    #pragma unroll
    for (int off = 16; off; off >>= 1) ss += __shfl_xor_sync(0xffffffffu, ss, off);

    #pragma unroll
    for (int i = 0; i < 16; i++)
        *(float2*)&OS[wid][lane][2 * i] = make_float2(oa[2 * i] * c, oa[2 * i + 1] * c);
    __syncwarp();

    float accd = 0.f;
    #pragma unroll
    for (int m = 0; m < 32; m++) accd += OS[wid][m][lane];
    if (valid)
        o16[(size_t)(ro + n) * QKVD + h * KDIM + lane] = __float2half_rn(accd / ss);
}

// LN finish: write fp32 h and fp16 h16
__device__ __forceinline__ void ln_finish(float v0, float v1, int n, int t,
                                          float* red, float* statp,
                                          float* __restrict__ h, __half* __restrict__ h16,
                                          const float* __restrict__ g,
                                          const float* __restrict__ b) {
    float s = v0 + v1;
    #pragma unroll
    for (int o = 16; o; o >>= 1) s += __shfl_xor_sync(0xffffffffu, s, o);
    if ((t & 31) == 0) red[t >> 5] = s;
    __syncthreads();
    if (t < 32) {
        float x = (t < 8) ? red[t] : 0.f;
        #pragma unroll
        for (int o = 4; o; o >>= 1) x += __shfl_xor_sync(0xffffffffu, x, o);
        if (t == 0) *statp = x / (float)DMODEL;
    }
    __syncthreads();
    float mean = *statp;
    float dd0 = v0 - mean, dd1 = v1 - mean;
    __syncthreads();
    float vs = dd0 * dd0 + dd1 * dd1;
    #pragma unroll
    for (int o = 16; o; o >>= 1) vs += __shfl_xor_sync(0xffffffffu, vs, o);
    if ((t & 31) == 0) red[t >> 5] = vs;
    __syncthreads();
    if (t < 32) {
        float x = (t < 8) ? red[t] : 0.f;
        #pragma unroll
        for (int o = 4; o; o >>= 1) x += __shfl_xor_sync(0xffffffffu, x, o);
        if (t == 0) *statp = rsqrtf(x / (float)DMODEL + LN_EPS);
    }
    __syncthreads();
    float rstd = *statp;
    float o0 = dd0 * rstd * g[t] + b[t];
    float o1 = dd1 * rstd * g[t + 256] + b[t + 256];
    h[n * DMODEL + t] = o0;
    h[n * DMODEL + t + 256] = o1;
    h16[n * DMODEL + t] = __float2half_rn(o0);
    h16[n * DMODEL + t + 256] = __float2half_rn(o1);
}

// comb partials (3 scales, upsampled) + residual + LN
__global__ void reduce_comb_ln(const float* __restrict__ P,
                               const float* __restrict__ bias,
                               float* __restrict__ h, __half* __restrict__ h16,
                               const float* __restrict__ g,
                               const float* __restrict__ b) {
    int n = blockIdx.x, t = threadIdx.x;
    __shared__ float red[8];
    __shared__ float stat;
    const size_t ND = (size_t)NPATCH * DMODEL;
    const int n2 = n >> 1, n4 = n >> 2;
    float v0 = h[n * DMODEL + t]       + bias[t];
    float v1 = h[n * DMODEL + t + 256] + bias[t + 256];
    v0 += P[0 * ND + (size_t)n  * DMODEL + t];
    v1 += P[0 * ND + (size_t)n  * DMODEL + t + 256];
    v0 += P[1 * ND + (size_t)n2 * DMODEL + t];
    v1 += P[1 * ND + (size_t)n2 * DMODEL + t + 256];
    v0 += P[2 * ND + (size_t)n4 * DMODEL + t];
    v1 += P[2 * ND + (size_t)n4 * DMODEL + t + 256];
    ln_finish(v0, v1, n, t, red, &stat, h, h16, g, b);
}

// ffn2 partials + residual + LN
__global__ void reduce_add_ln(const float* __restrict__ part, int S,
                              const float* __restrict__ bias,
                              float* __restrict__ h, __half* __restrict__ h16,
                              const float* __restrict__ g,
                              const float* __restrict__ b) {
    int n = blockIdx.x, t = threadIdx.x;
    __shared__ float red[8];
    __shared__ float stat;
    float v0 = h[n * DMODEL + t]       + bias[t];
    float v1 = h[n * DMODEL + t + 256] + bias[t + 256];
    for (int s = 0; s < S; s++) {
        v0 += part[(size_t)s * NPATCH * DMODEL + n * DMODEL + t];
        v1 += part[(size_t)s * NPATCH * DMODEL + n * DMODEL + t + 256];
    }
    ln_finish(v0, v1, n, t, red, &stat, h, h16, g, b);
}

// fused global-mean-pool + head + softmax + broadcast
__global__ void head_kernel(const float* __restrict__ h, const float* __restrict__ W,
                            const float* __restrict__ b, float* __restrict__ out) {
    __shared__ float gs[DMODEL];
    __shared__ float red[8];
    __shared__ float stat;
    int t = threadIdx.x;  // 256
    {
        float s0 = 0.f, s1 = 0.f;
        for (int n = 0; n < NPATCH; n++) {
            s0 += h[n * DMODEL + t];
            s1 += h[n * DMODEL + t + 256];
        }
        gs[t] = s0 / (float)NPATCH;
        gs[t + 256] = s1 / (float)NPATCH;
    }
    __syncthreads();
    float acc = b[t];
    #pragma unroll 4
    for (int d = 0; d < DMODEL; d++) acc += gs[d] * W[d * NCLS + t];

    float m = acc;
    #pragma unroll
    for (int o = 16; o; o >>= 1) m = fmaxf(m, __shfl_xor_sync(0xffffffffu, m, o));
    if ((t & 31) == 0) red[t >> 5] = m;
    __syncthreads();
    if (t < 32) {
        float x = (t < 8) ? red[t] : -INFINITY;
        #pragma unroll
        for (int o = 4; o; o >>= 1) x = fmaxf(x, __shfl_xor_sync(0xffffffffu, x, o));
        if (t == 0) stat = x;
    }
    __syncthreads();
    float e = expf(acc - stat);
    __syncthreads();
    float s = e;
    #pragma unroll
    for (int o = 16; o; o >>= 1) s += __shfl_xor_sync(0xffffffffu, s, o);
    if ((t & 31) == 0) red[t >> 5] = s;
    __syncthreads();
    if (t < 32) {
        float x = (t < 8) ? red[t] : 0.f;
        #pragma unroll
        for (int o = 4; o; o >>= 1) x += __shfl_xor_sync(0xffffffffu, x, o);
        if (t == 0) stat = x;
    }
    __syncthreads();
    float p = e / stat;
    for (int bb = 0; bb < NBATCH; bb++) out[bb * NCLS + t] = p;
}

// ---------------- host launcher ----------------
extern "C" void kernel_launch(void* const* d_in, const int* in_sizes, int n_in,
                              void* d_out, int out_size) {
    const float* ln_in_b = (const float*)d_in[2];
    const float* patch_W = (const float*)d_in[3];
    const float* patch_b = (const float*)d_in[4];
    const float* pos_emb = (const float*)d_in[5];
    const float* Wq = (const float*)d_in[6];
    const float* bq = (const float*)d_in[7];
    const float* Wk = (const float*)d_in[8];
    const float* bk = (const float*)d_in[9];
    const float* Wv = (const float*)d_in[10];
    const float* bv = (const float*)d_in[11];
    const float* Wo = (const float*)d_in[12];
    const float* bo = (const float*)d_in[13];
    const float* Wc = (const float*)d_in[14];
    const float* bc = (const float*)d_in[15];
    const float* ln1_g = (const float*)d_in[16];
    const float* ln1_b = (const float*)d_in[17];
    const float* W1 = (const float*)d_in[18];
    const float* b1 = (const float*)d_in[19];
    const float* W2 = (const float*)d_in[20];
    const float* b2 = (const float*)d_in[21];
    const float* ln2_g = (const float*)d_in[22];
    const float* ln2_b = (const float*)d_in[23];
    const float* head_W = (const float*)d_in[24];
    const float* head_b = (const float*)d_in[25];
    float* out = (float*)d_out;

    float *hp, *qp, *kp, *vp, *partp, *csp;
    __half *h16p, *pool16p, *o16p, *ao16p, *ff16p;
    __half *wq16, *wk16, *wv16, *wo16, *wc16, *w116, *w216;
    cudaGetSymbolAddress((void**)&hp,  d_h);
    cudaGetSymbolAddress((void**)&h16p, d_h16);
    cudaGetSymbolAddress((void**)&pool16p, d_pool16);
    cudaGetSymbolAddress((void**)&qp,  d_q);
    cudaGetSymbolAddress((void**)&kp,  d_k);
    cudaGetSymbolAddress((void**)&vp,  d_v);
    cudaGetSymbolAddress((void**)&o16p, d_o16);
    cudaGetSymbolAddress((void**)&ao16p, d_ao16);
    cudaGetSymbolAddress((void**)&ff16p, d_ff16);
    cudaGetSymbolAddress((void**)&partp, d_part);
    cudaGetSymbolAddress((void**)&csp, d_cs);
    cudaGetSymbolAddress((void**)&wq16, d_Wq16);
    cudaGetSymbolAddress((void**)&wk16, d_Wk16);
    cudaGetSymbolAddress((void**)&wv16, d_Wv16);
    cudaGetSymbolAddress((void**)&wo16, d_Wo16);
    cudaGetSymbolAddress((void**)&wc16, d_Wc16);
    cudaGetSymbolAddress((void**)&w116, d_W116);
    cudaGetSymbolAddress((void**)&w216, d_W216);

    dim3 tb(32, 8);
    transconv<<<dim3(QKVD / 32, DMODEL / 32, 18), tb>>>(Wq, wq16, DMODEL, QKVD);
    transconv<<<dim3(QKVD / 32, DMODEL / 32, 18), tb>>>(Wk, wk16, DMODEL, QKVD);
    transconv<<<dim3(QKVD / 32, DMODEL / 32, 18), tb>>>(Wv, wv16, DMODEL, QKVD);
    transconv<<<dim3(DMODEL / 32, QKVD / 32, 18), tb>>>(Wo, wo16, QKVD, DMODEL);
    transconv<<<dim3(DMODEL / 32, DMODEL / 32, 18), tb>>>(Wc, wc16, DMODEL, DMODEL);
    transconv<<<dim3(FFD / 32, DMODEL / 32, 6), tb>>>(W1, w116, DMODEL, FFD);
    transconv<<<dim3(DMODEL / 32, FFD / 32, 6), tb>>>(W2, w216, FFD, DMODEL);

    colsum_kernel<<<1, DMODEL>>>(patch_W, csp);
    init_h_kernel<<<NPATCH, DMODEL>>>(csp, ln_in_b, patch_b, pos_emb, hp, h16p);

    for (int l = 0; l < NLAYER; l++) {
        size_t bqkv = (size_t)l * 3 * QKVD;
        size_t bwo  = (size_t)l * 3 * DMODEL;

        pool_kernel<<<375, DMODEL>>>(hp, pool16p);
        gemm_qkv<<<dim3(3, 8, 9), 256, SMEMB>>>(h16p, pool16p,
            wq16 + (size_t)l * 3 * QKVD * DMODEL,
            wk16 + (size_t)l * 3 * QKVD * DMODEL,
            wv16 + (size_t)l * 3 * QKVD * DMODEL,
            bq + bqkv, bk + bqkv, bv + bqkv, qp, kp, vp);
        attn_kernel<<<555, 256>>>(qp, kp, vp, o16p);
        gemm_wo<<<dim3(8, 8, 3), 256, SMEMB>>>(o16p,
            wo16 + (size_t)l * 3 * DMODEL * QKVD, bo + bwo, ao16p);

        gemm_comb<<<dim3(8, 8, 3), 256, SMEMB>>>(ao16p,
            wc16 + (size_t)l * 3 * DMODEL * DMODEL, partp);
        reduce_comb_ln<<<NPATCH, 256>>>(partp, bc + (size_t)l * DMODEL, hp, h16p,
                                        ln1_g + l * DMODEL, ln1_b + l * DMODEL);

        gemm_ffn1<<<dim3(32, 8), 256, SMEMB>>>(h16p,
            w116 + (size_t)l * FFD * DMODEL, b1 + (size_t)l * FFD, ff16p);
        gemm_ffn2<<<dim3(8, 8, 4), 256, SMEMB>>>(ff16p,
            w216 + (size_t)l * DMODEL * FFD, partp);
        reduce_add_ln<<<NPATCH, 256>>>(partp, 4, b2 + (size_t)l * DMODEL, hp, h16p,
                                       ln2_g + l * DMODEL, ln2_b + l * DMODEL);
    }

    head_kernel<<<1, NCLS>>>(hp, head_W, head_b, out);
}